// round 9
// baseline (speedup 1.0000x reference)
#include <cuda_runtime.h>
#include <cuda_fp16.h>
#include <cstdint>

#define BSZ 32
#define CIc 32
#define PP  256

__device__ short g_votes[BSZ*32*CIc*8*PP];   // [b][co][ci][no][p], value*256 (exact)
__device__ float g_logits[BSZ*CIc*32*PP];    // [b][ci][co][p]
__device__ float g_smax[BSZ*CIc];
__device__ float g_ssum[BSZ*CIc];
__device__ uint4  g_wsplit[4608];            // W fp16: hi rows [0,36864), lo [36864,73728), 144B rows
__device__ __half g_xh[BSZ*CIc*2048];        // x fp16 hi, [b][ci][ni][16][16]
__device__ __half g_xl[BSZ*CIc*2048];        // x fp16 lo

// ---------------- helpers ----------------
static __device__ __forceinline__ uint32_t smem_u32(const void* p) {
    uint32_t a;
    asm("{ .reg .u64 t; cvta.to.shared.u64 t, %1; cvt.u32.u64 %0, t; }" : "=r"(a) : "l"(p));
    return a;
}

#define MMA16816(d, a, b) \
    asm volatile("mma.sync.aligned.m16n8k16.row.col.f32.f16.f16.f32 " \
        "{%0,%1,%2,%3}, {%4,%5,%6,%7}, {%8,%9}, {%0,%1,%2,%3};" \
        : "+f"((d)[0]), "+f"((d)[1]), "+f"((d)[2]), "+f"((d)[3]) \
        : "r"((a)[0]), "r"((a)[1]), "r"((a)[2]), "r"((a)[3]), "r"((b)[0]), "r"((b)[1]))

#define MMA1688(d, a0, a1, b0) \
    asm volatile("mma.sync.aligned.m16n8k8.row.col.f32.f16.f16.f32 " \
        "{%0,%1,%2,%3}, {%4,%5}, {%6}, {%0,%1,%2,%3};" \
        : "+f"((d)[0]), "+f"((d)[1]), "+f"((d)[2]), "+f"((d)[3]) \
        : "r"(a0), "r"(a1), "r"(b0))

#define LDMX4(r0, r1, r2, r3, addr) \
    asm volatile("ldmatrix.sync.aligned.m8n8.x4.shared.b16 {%0,%1,%2,%3}, [%4];" \
        : "=r"(r0), "=r"(r1), "=r"(r2), "=r"(r3) : "r"(addr))

static __device__ __forceinline__ uint32_t packh(__half a, __half b) {
    return (uint32_t)__half_as_ushort(a) | ((uint32_t)__half_as_ushort(b) << 16);
}
// rn fp16 2-term split of a float pair; returns hi pair, writes lo pair.
static __device__ __forceinline__ uint32_t packsplit(float f0, float f1, uint32_t &lo) {
    __half h0 = __float2half_rn(f0), h1 = __float2half_rn(f1);
    __half l0 = __float2half_rn(__fsub_rn(f0, __half2float(h0)));
    __half l1 = __float2half_rn(__fsub_rn(f1, __half2float(h1)));
    lo = packh(l0, l1);
    return packh(h0, h1);
}

// 144B rows (72 fp16 exactly, no pad). Bank step 4i mod 32 -> distinct within
// each 8-row ldmatrix group => conflict-free. k8 tail = last 16B of the row.
#define ROWB       144u
#define BHI_OFF    0u                       // [128 o][144B]
#define BLO_OFF    18432u
#define AHI_OFF    36864u                   // [128 p][144B]
#define ALO_OFF    55296u
#define XSH_OFF    73728u                   // x tile halves [8ni][10][18] shorts
#define XSL_OFF    76608u
#define CBS_OFF    79488u                   // 256 floats
#define A1S_OFF    80512u                   // 256 ints
#define KLUT_OFF   81536u                   // 72 ints
#define CONV_SMEM  81840

__global__ void noop_kernel() {}

// ---------------------------------------------------------------------------
// Prep 1: W -> fp16 hi/lo in final ldmatrix row layout (144B rows)
// ---------------------------------------------------------------------------
__global__ void __launch_bounds__(256) prep_w_kernel(const float* __restrict__ w)
{
    const int o = threadIdx.x;
    const float4* wr = (const float4*)(w + o*72);
    char* bh = (char*)g_wsplit + o*ROWB;
    char* bl = (char*)g_wsplit + 36864 + o*ROWB;
    #pragma unroll
    for (int q = 0; q < 18; q++) {
        float4 v = wr[q];
        uint32_t l0, l1;
        uint32_t h0 = packsplit(v.x, v.y, l0);
        uint32_t h1 = packsplit(v.z, v.w, l1);
        *(uint2*)(bh + q*8) = make_uint2(h0, h1);
        *(uint2*)(bl + q*8) = make_uint2(l0, l1);
    }
}

// ---------------------------------------------------------------------------
// Prep 2: x -> fp16 hi/lo (per-element split, before im2col)
// ---------------------------------------------------------------------------
__global__ void __launch_bounds__(256) prep_x_kernel(const float* __restrict__ x)
{
    const int tile = blockIdx.x;           // b*32 + ci
    const float4* src = (const float4*)(x + tile*2048);
    #pragma unroll
    for (int i = 0; i < 2; i++) {
        int idx4 = threadIdx.x + i*256;
        float4 v = src[idx4];
        uint32_t l0, l1;
        uint32_t h0 = packsplit(v.x, v.y, l0);
        uint32_t h1 = packsplit(v.z, v.w, l1);
        *(uint2*)(g_xh + tile*2048 + idx4*4) = make_uint2(h0, h1);
        *(uint2*)(g_xl + tile*2048 + idx4*4) = make_uint2(l0, l1);
    }
}

// ---------------------------------------------------------------------------
// Kernel 1: fp16-split mma.sync conv -> int16 votes + iteration-1 logits.
// block = (b, ci, ph, oh): 128p x 128o quarter tile, 256 thr / 8 warps.
// Warp tile 32p x 64o (2 passes of 32o). K = 72: 4 x k16 + 1 x k8, 3 products.
// smem 82KB -> 2 CTAs/SM (prologue of one block overlaps MMAs of the other).
// ---------------------------------------------------------------------------
__global__ void __launch_bounds__(256, 2) conv_votes_kernel(
    const float* __restrict__ cb, const float* __restrict__ bias)
{
    extern __shared__ char sh[];
    float* cbs = (float*)(sh + CBS_OFF);
    int*   a1s = (int*)(sh + A1S_OFF);
    int*   klut= (int*)(sh + KLUT_OFF);
    const uint32_t smb = smem_u32(sh);

    const int t = threadIdx.x;
    const int wid = t >> 5, lane = t & 31;
    const int blk = blockIdx.x;
    const int tile = blk >> 2;                 // b*32 + ci
    const int b = blk >> 7, ci = (blk >> 2) & 31;
    const int ph = (blk >> 1) & 1, oh = blk & 1;

    // --- phase 0: B copy (this o-half), zero x pads, constants ---
    {
        const uint4* srcH = g_wsplit + (oh*18432)/16;
        const uint4* srcL = g_wsplit + (36864 + oh*18432)/16;
        uint4* dstH = (uint4*)(sh + BHI_OFF);
        uint4* dstL = (uint4*)(sh + BLO_OFF);
        #pragma unroll
        for (int i = 0; i < 5; i++) {          // 1152 uint4 each half
            int idx = t + i*256;
            if (idx < 1152) { dstH[idx] = srcH[idx]; dstL[idx] = srcL[idx]; }
        }
    }
    {   // zero both x tile halves: 2*1440 shorts = 1440 u32
        uint32_t* z = (uint32_t*)(sh + XSH_OFF);
        #pragma unroll
        for (int i = 0; i < 6; i++) {
            int idx = t + i*256;
            if (idx < 1440) z[idx] = 0;
        }
    }
    if (t < 256) cbs[t] = cb[t];
    if (t < 72) { int ni = t/9, r = t%9; klut[t] = ni*180 + (r/3)*18 + (r%3); }
    if (t < 32) {   // iteration-1 activation from bias (quant(route)==0)
        float pv[8]; float ss = 0.f;
        #pragma unroll
        for (int no = 0; no < 8; no++) {
            float q = rintf(__fmul_rn(bias[t*8+no], 256.f)) * 0.00390625f;
            pv[no] = q; ss = __fadd_rn(ss, __fmul_rn(q, q));
        }
        float n = sqrtf(ss);
        float den = __fadd_rn(1.f, __fmul_rn(n, n));
        #pragma unroll
        for (int no = 0; no < 8; no++) {
            float a = __fdiv_rn(__fmul_rn(pv[no], n), den);
            a1s[t*8+no] = __float2int_rn(__fmul_rn(a, 256.f));
        }
    }
    __syncthreads();

    // --- phase 1: x tile rows with halo: xs row yy <-> global row ph*8-1+yy ---
    {
        const __half* xh = g_xh + tile*2048;
        const __half* xl = g_xl + tile*2048;
        unsigned short* dh = (unsigned short*)(sh + XSH_OFF);
        unsigned short* dl = (unsigned short*)(sh + XSL_OFF);
        #pragma unroll
        for (int i = 0; i < 5; i++) {          // 1280 interior elements per half
            int idx = t + i*256;
            int ni = idx / 160, r = idx % 160;
            int yy = r >> 4, col = r & 15;
            int g = ph*8 - 1 + yy;
            if (g >= 0 && g < 16) {
                int dsto = ni*180 + yy*18 + col + 1;
                int srco = ni*256 + g*16 + col;
                dh[dsto] = __half_as_ushort(xh[srco]);
                dl[dsto] = __half_as_ushort(xl[srco]);
            }
        }
    }
    __syncthreads();

    // --- phase 2: A build (im2col gather of pre-split halves) ---
    {
        const int p = t & 127;
        const unsigned short* xsrc = (unsigned short*)(sh + ((t < 128) ? XSH_OFF : XSL_OFF));
        char* dst = sh + ((t < 128) ? AHI_OFF : ALO_OFF) + p*ROWB;
        const int xyb = (p >> 4)*18 + (p & 15);
        #pragma unroll
        for (int q = 0; q < 9; q++) {
            uint32_t u[4];
            #pragma unroll
            for (int j = 0; j < 4; j++) {
                uint32_t v0 = xsrc[klut[q*8 + 2*j]     + xyb];
                uint32_t v1 = xsrc[klut[q*8 + 2*j + 1] + xyb];
                u[j] = v0 | (v1 << 16);
            }
            *(uint4*)(dst + q*16) = make_uint4(u[0], u[1], u[2], u[3]);
        }
    }
    __syncthreads();

    // --- MMA: warp w -> p-subtile (w&3)*32, o-subtile (w>>2)*64, 2 o-passes ---
    const int pbase = (wid & 3)*32;
    const int obase = (wid >> 2)*64;
    const int lane2 = (lane & 3)*2;

    #pragma unroll 1
    for (int pass = 0; pass < 2; pass++) {
        const int ob = obase + pass*32;        // local o tile base
        float acc[2][4][4];
        #pragma unroll
        for (int mt = 0; mt < 2; mt++)
            #pragma unroll
            for (int nt = 0; nt < 4; nt++)
                #pragma unroll
                for (int j = 0; j < 4; j++) acc[mt][nt][j] = 0.f;

        #pragma unroll
        for (int kc = 0; kc < 5; kc++) {
            uint32_t ah[2][4], al[2][4];
            #pragma unroll
            for (int mt = 0; mt < 2; mt++) {
                const uint32_t arow = pbase + mt*16 + (lane & 15);
                const uint32_t aoff = arow*ROWB + kc*32 + ((lane >> 4) << 4);
                LDMX4(ah[mt][0], ah[mt][1], ah[mt][2], ah[mt][3], smb + AHI_OFF + aoff);
                LDMX4(al[mt][0], al[mt][1], al[mt][2], al[mt][3], smb + ALO_OFF + aoff);
            }
            uint32_t bh[4][2], bl[4][2];
            #pragma unroll
            for (int g = 0; g < 2; g++) {
                const uint32_t row = ob + g*16 + (lane & 7) + ((lane >> 4) << 3);
                const uint32_t koff = kc*32 + ((lane >> 3) & 1)*16;
                LDMX4(bh[2*g][0], bh[2*g][1], bh[2*g+1][0], bh[2*g+1][1],
                      smb + BHI_OFF + row*ROWB + koff);
                LDMX4(bl[2*g][0], bl[2*g][1], bl[2*g+1][0], bl[2*g+1][1],
                      smb + BLO_OFF + row*ROWB + koff);
            }
            if (kc < 4) {
                #pragma unroll
                for (int mt = 0; mt < 2; mt++)
                    #pragma unroll
                    for (int nt = 0; nt < 4; nt++) {
                        MMA16816(acc[mt][nt], ah[mt], bh[nt]);
                        MMA16816(acc[mt][nt], ah[mt], bl[nt]);
                        MMA16816(acc[mt][nt], al[mt], bh[nt]);
                    }
            } else {   // k 64..71: m16n8k8 (pad products would be exact zeros)
                #pragma unroll
                for (int mt = 0; mt < 2; mt++)
                    #pragma unroll
                    for (int nt = 0; nt < 4; nt++) {
                        MMA1688(acc[mt][nt], ah[mt][0], ah[mt][1], bh[nt][0]);
                        MMA1688(acc[mt][nt], ah[mt][0], ah[mt][1], bl[nt][0]);
                        MMA1688(acc[mt][nt], al[mt][0], al[mt][1], bh[nt][0]);
                    }
            }
        }

        // --- epilogue: quant votes direct-to-global + quad-shuffle logit fold ---
        #pragma unroll
        for (int mt = 0; mt < 2; mt++) {
            const int p0 = ph*128 + pbase + mt*16 + (lane >> 2);
            #pragma unroll
            for (int nt = 0; nt < 4; nt++) {
                const int o = oh*128 + ob + nt*8 + lane2;   // even: o,o+1 share co
                const float cb0 = cbs[o], cb1 = cbs[o+1];
                int v0 = __float2int_rn((acc[mt][nt][0] + cb0) * 256.f);
                int v1 = __float2int_rn((acc[mt][nt][1] + cb1) * 256.f);
                int v2 = __float2int_rn((acc[mt][nt][2] + cb0) * 256.f);
                int v3 = __float2int_rn((acc[mt][nt][3] + cb1) * 256.f);
                short* vb = g_votes + ((size_t)b << 21) + (o >> 3)*65536
                          + ci*2048 + (o & 7)*256;
                vb[p0]           = (short)v0;
                vb[256 + p0]     = (short)v1;
                vb[p0 + 8]       = (short)v2;
                vb[256 + p0 + 8] = (short)v3;
                int s0 = a1s[o]*v0 + a1s[o+1]*v1;
                int s1 = a1s[o]*v2 + a1s[o+1]*v3;
                s0 += __shfl_xor_sync(0xffffffffu, s0, 1);
                s0 += __shfl_xor_sync(0xffffffffu, s0, 2);
                s1 += __shfl_xor_sync(0xffffffffu, s1, 1);
                s1 += __shfl_xor_sync(0xffffffffu, s1, 2);
                if ((lane & 3) == 0) {
                    float* lb = g_logits + ((b*32 + ci)*32 + (o >> 3))*256;
                    lb[p0]     = rintf((float)s0 * 0.00390625f) * 0.00390625f;
                    lb[p0 + 8] = rintf((float)s1 * 0.00390625f) * 0.00390625f;
                }
            }
        }
    }
}

// ---------------------------------------------------------------------------
// Kernel 2: softmax stats per (b, ci) over 8192 logits
// ---------------------------------------------------------------------------
__global__ void __launch_bounds__(256) softmax_kernel()
{
    const int row = blockIdx.x;
    const float* lp = g_logits + row*8192;
    const int t = threadIdx.x;
    float fl[32];
    #pragma unroll
    for (int i = 0; i < 32; i++) fl[i] = lp[i*256 + t];
    float m = fl[0];
    #pragma unroll
    for (int i = 1; i < 32; i++) m = fmaxf(m, fl[i]);
    __shared__ float red[8];
    #pragma unroll
    for (int off = 16; off; off >>= 1) m = fmaxf(m, __shfl_xor_sync(0xffffffffu, m, off));
    if ((t & 31) == 0) red[t >> 5] = m;
    __syncthreads();
    float M = red[0];
    #pragma unroll
    for (int i = 1; i < 8; i++) M = fmaxf(M, red[i]);
    __syncthreads();
    float s = 0.f;
    #pragma unroll
    for (int i = 0; i < 32; i++) s += expf(fl[i] - M);
    #pragma unroll
    for (int off = 16; off; off >>= 1) s += __shfl_xor_sync(0xffffffffu, s, off);
    if ((t & 31) == 0) red[t >> 5] = s;
    __syncthreads();
    if (t == 0) {
        float S = red[0];
        for (int i = 1; i < 8; i++) S += red[i];
        g_smax[row] = M;
        g_ssum[row] = S;
    }
}

// ---------------------------------------------------------------------------
// Kernel 3: fused routing iteration. block = (b, co, p-half); 128 threads.
// ---------------------------------------------------------------------------
__global__ void __launch_bounds__(128) route_kernel(
    const float* __restrict__ bias, float* __restrict__ out, int last)
{
    extern __shared__ char shb[];
    short* sv    = (short*)shb;                 // [32ci][8no][128p] = 65536 B
    float* smaxs = (float*)(shb + 65536);
    float* ssums = (float*)(shb + 65664);
    float* sb    = (float*)(shb + 65792);

    const int t   = threadIdx.x;
    const int blk = blockIdx.x;
    const int bco = blk >> 1, ph = blk & 1;
    const int b   = bco >> 5, co = bco & 31;

    {
        const short* src0 = g_votes + (size_t)bco*65536 + ph*128;
        uint4* dst = (uint4*)sv;
        #pragma unroll
        for (int r = 0; r < 32; r++) {
            int idx = r*128 + t;
            int cino = idx >> 4, ch = idx & 15;
            dst[idx] = *(const uint4*)(src0 + cino*256 + ch*8);
        }
    }
    if (t < 32) { smaxs[t] = g_smax[b*32 + t]; ssums[t] = g_ssum[b*32 + t]; }
    if (t < 8)  sb[t] = bias[co*8 + t];
    __syncthreads();

    float l[32];
    int S[8] = {0,0,0,0,0,0,0,0};
    const float* lgp = g_logits + (b*32)*8192 + co*256 + ph*128 + t;
    #pragma unroll
    for (int c = 0; c < 32; c++) {
        float lv = lgp[c*8192];
        l[c] = lv;
        float e = expf(lv - smaxs[c]);
        int r = __float2int_rn(__fmul_rn(__fdiv_rn(e, ssums[c]), 256.f));
        if (r) {
            #pragma unroll
            for (int no = 0; no < 8; no++)
                S[no] += r * (int)sv[(c*8 + no)*128 + t];
        }
    }
    float pq[8]; float ss = 0.f;
    #pragma unroll
    for (int no = 0; no < 8; no++) {
        float pre = __fadd_rn(__fmul_rn((float)S[no], 1.52587890625e-05f), sb[no]);
        float q = rintf(__fmul_rn(pre, 256.f)) * 0.00390625f;
        pq[no] = q; ss = __fadd_rn(ss, __fmul_rn(q, q));
    }
    float n   = sqrtf(ss);
    float den = __fadd_rn(1.f, __fmul_rn(n, n));
    int ai[8];
    #pragma unroll
    for (int no = 0; no < 8; no++) {
        float a = __fdiv_rn(__fmul_rn(pq[no], n), den);
        int q = __float2int_rn(__fmul_rn(a, 256.f));
        ai[no] = q;
        out[(bco*8 + no)*256 + ph*128 + t] = (float)q * 0.00390625f;
    }
    if (!last) {
        float* lw = g_logits + (b*32)*8192 + co*256 + ph*128 + t;
        #pragma unroll
        for (int c = 0; c < 32; c++) {
            int m = 0;
            #pragma unroll
            for (int no = 0; no < 8; no++)
                m += ai[no] * (int)sv[(c*8 + no)*128 + t];
            float lg = __fadd_rn(l[c], __fmul_rn((float)m, 1.52587890625e-05f));
            lw[c*8192] = rintf(__fmul_rn(lg, 256.f)) * 0.00390625f;
        }
    }
}

// ---------------------------------------------------------------------------
extern "C" void kernel_launch(void* const* d_in, const int* in_sizes, int n_in,
                              void* d_out, int out_size)
{
    const float* x    = (const float*)d_in[0];
    const float* w    = (const float*)d_in[1];
    const float* cb   = (const float*)d_in[2];
    const float* bias = (const float*)d_in[3];
    float* out = (float*)d_out;
    (void)in_sizes; (void)n_in; (void)out_size;

    const int ROUTE_SMEM = 65824;
    cudaFuncSetAttribute(conv_votes_kernel, cudaFuncAttributeMaxDynamicSharedMemorySize, CONV_SMEM);
    cudaFuncSetAttribute(route_kernel,      cudaFuncAttributeMaxDynamicSharedMemorySize, ROUTE_SMEM);

    prep_w_kernel<<<1, 256>>>(w);          // launch 1
    prep_x_kernel<<<1024, 256>>>(x);       // launch 2
    noop_kernel<<<1, 32>>>();              // launches 3-5: shift ncu (-s 5) onto conv
    noop_kernel<<<1, 32>>>();
    noop_kernel<<<1, 32>>>();
    conv_votes_kernel<<<4096, 256, CONV_SMEM>>>(cb, bias);   // launch 6 -> profiled
    softmax_kernel<<<1024, 256>>>();                         // iteration 2
    route_kernel<<<2048, 128, ROUTE_SMEM>>>(bias, out, 0);
    softmax_kernel<<<1024, 256>>>();                         // iteration 3
    route_kernel<<<2048, 128, ROUTE_SMEM>>>(bias, out, 1);
}

// round 10
// speedup vs baseline: 1.0240x; 1.0240x over previous
#include <cuda_runtime.h>
#include <cuda_fp16.h>
#include <cstdint>

#define BSZ 32
#define CIc 32
#define PP  256

__device__ short g_votes[BSZ*32*CIc*8*PP];   // [b][co][ci][no][p], value*256 (exact)
__device__ float g_logits[BSZ*CIc*32*PP];    // [b][ci][co][p]
__device__ float g_smax[BSZ*CIc];
__device__ float g_ssum[BSZ*CIc];
__device__ uint4  g_wsplit[5632];            // W fp16 hi[0..45056) lo[45056..90112), 176B rows
__device__ __half g_xh[BSZ*CIc*2048];        // x fp16 hi, [b][ci][ni][16][16]
__device__ __half g_xl[BSZ*CIc*2048];        // x fp16 lo

// ---------------- helpers ----------------
static __device__ __forceinline__ uint32_t smem_u32(const void* p) {
    uint32_t a;
    asm("{ .reg .u64 t; cvta.to.shared.u64 t, %1; cvt.u32.u64 %0, t; }" : "=r"(a) : "l"(p));
    return a;
}

#define MMA16816(d, a, b) \
    asm volatile("mma.sync.aligned.m16n8k16.row.col.f32.f16.f16.f32 " \
        "{%0,%1,%2,%3}, {%4,%5,%6,%7}, {%8,%9}, {%0,%1,%2,%3};" \
        : "+f"((d)[0]), "+f"((d)[1]), "+f"((d)[2]), "+f"((d)[3]) \
        : "r"((a)[0]), "r"((a)[1]), "r"((a)[2]), "r"((a)[3]), "r"((b)[0]), "r"((b)[1]))

#define MMA1688(d, a0, a1, b0) \
    asm volatile("mma.sync.aligned.m16n8k8.row.col.f32.f16.f16.f32 " \
        "{%0,%1,%2,%3}, {%4,%5}, {%6}, {%0,%1,%2,%3};" \
        : "+f"((d)[0]), "+f"((d)[1]), "+f"((d)[2]), "+f"((d)[3]) \
        : "r"(a0), "r"(a1), "r"(b0))

#define LDMX4(r0, r1, r2, r3, addr) \
    asm volatile("ldmatrix.sync.aligned.m8n8.x4.shared.b16 {%0,%1,%2,%3}, [%4];" \
        : "=r"(r0), "=r"(r1), "=r"(r2), "=r"(r3) : "r"(addr))

static __device__ __forceinline__ uint32_t packh(__half a, __half b) {
    return (uint32_t)__half_as_ushort(a) | ((uint32_t)__half_as_ushort(b) << 16);
}
// rn fp16 2-term split of a float pair; returns hi pair, writes lo pair.
static __device__ __forceinline__ uint32_t packsplit(float f0, float f1, uint32_t &lo) {
    __half h0 = __float2half_rn(f0), h1 = __float2half_rn(f1);
    __half l0 = __float2half_rn(__fsub_rn(f0, __half2float(h0)));
    __half l1 = __float2half_rn(__fsub_rn(f1, __half2float(h1)));
    lo = packh(l0, l1);
    return packh(h0, h1);
}

// 176B rows: 44*i mod 32 covers all banks -> ldmatrix conflict-free
#define ROWB       176u
#define BHI_OFF    0u                       // [256 o][176B]
#define BLO_OFF    45056u
#define AHI_OFF    90112u                   // [256 p][176B]
#define ALO_OFF    135168u
#define XSH_OFF    180224u                  // padded x tile halves [8][18][18]
#define XSL_OFF    185408u
#define CBS_OFF    190592u                  // 256 floats
#define A1S_OFF    191616u                  // 256 ints
#define KLUT_OFF   192640u                  // 72 ints
#define CONV_SMEM  192928

__global__ void noop_kernel() {}

// ---------------------------------------------------------------------------
// Prep 1: W -> fp16 hi/lo in final ldmatrix row layout (one block, once)
// ---------------------------------------------------------------------------
__global__ void __launch_bounds__(256) prep_w_kernel(const float* __restrict__ w)
{
    const int o = threadIdx.x;
    const float4* wr = (const float4*)(w + o*72);
    char* bh = (char*)g_wsplit + o*ROWB;
    char* bl = (char*)g_wsplit + 45056 + o*ROWB;
    #pragma unroll
    for (int q = 0; q < 18; q++) {
        float4 v = wr[q];
        uint32_t l0, l1;
        uint32_t h0 = packsplit(v.x, v.y, l0);
        uint32_t h1 = packsplit(v.z, v.w, l1);
        *(uint2*)(bh + q*8) = make_uint2(h0, h1);
        *(uint2*)(bl + q*8) = make_uint2(l0, l1);
    }
    *(uint4*)(bh + 144) = make_uint4(0,0,0,0);
    *(uint4*)(bh + 160) = make_uint4(0,0,0,0);
    *(uint4*)(bl + 144) = make_uint4(0,0,0,0);
    *(uint4*)(bl + 160) = make_uint4(0,0,0,0);
}

// ---------------------------------------------------------------------------
// Prep 2: x -> fp16 hi/lo (per-element split, before im2col)
// ---------------------------------------------------------------------------
__global__ void __launch_bounds__(256) prep_x_kernel(const float* __restrict__ x)
{
    const int tile = blockIdx.x;           // b*32 + ci
    const float4* src = (const float4*)(x + tile*2048);
    #pragma unroll
    for (int i = 0; i < 2; i++) {
        int idx4 = threadIdx.x + i*256;
        float4 v = src[idx4];
        uint32_t l0, l1;
        uint32_t h0 = packsplit(v.x, v.y, l0);
        uint32_t h1 = packsplit(v.z, v.w, l1);
        *(uint2*)(g_xh + tile*2048 + idx4*4) = make_uint2(h0, h1);
        *(uint2*)(g_xl + tile*2048 + idx4*4) = make_uint2(l0, l1);
    }
}

// ---------------------------------------------------------------------------
// Kernel 1: fp16-split mma.sync conv -> int16 votes + iteration-1 logits.
// block = (b, ci), 512 threads / 16 warps. Warp tile 32p x 32o, 4 passes.
// K = 72 exact: 4 x k16 + 1 x k8. Products issued product-major (hh,hl,lh)
// to break per-accumulator RAW chains.
// ---------------------------------------------------------------------------
__global__ void __launch_bounds__(512, 1) conv_votes_kernel(
    const float* __restrict__ cb, const float* __restrict__ bias)
{
    extern __shared__ char sh[];
    float* cbs = (float*)(sh + CBS_OFF);
    int*   a1s = (int*)(sh + A1S_OFF);
    int*   klut= (int*)(sh + KLUT_OFF);
    const uint32_t smb = smem_u32(sh);

    const int t = threadIdx.x;
    const int wid = t >> 5, lane = t & 31;
    const int b = blockIdx.x >> 5, ci = blockIdx.x & 31;

    // --- phase 0: B copy (pure memcpy), zero x pads, constants ---
    {
        const uint4* src = g_wsplit;
        uint4* dst = (uint4*)sh;           // BHI/BLO contiguous [0, 90112)
        #pragma unroll
        for (int i = 0; i < 11; i++) dst[t + i*512] = src[t + i*512];
    }
    {   // zero both padded x tiles (2592 uints total across the two arrays)
        uint32_t* z = (uint32_t*)(sh + XSH_OFF);
        #pragma unroll
        for (int i = 0; i < 6; i++) {
            int idx = t + i*512;
            if (idx < 2592) z[idx] = 0;
        }
    }
    if (t < 256) cbs[t] = cb[t];
    if (t < 72) { int ni = t/9, r = t%9; klut[t] = ni*324 + (r/3)*18 + (r%3); }
    if (t < 32) {   // iteration-1 activation from bias (quant(route)==0)
        float pv[8]; float ss = 0.f;
        #pragma unroll
        for (int no = 0; no < 8; no++) {
            float q = rintf(__fmul_rn(bias[t*8+no], 256.f)) * 0.00390625f;
            pv[no] = q; ss = __fadd_rn(ss, __fmul_rn(q, q));
        }
        float n = sqrtf(ss);
        float den = __fadd_rn(1.f, __fmul_rn(n, n));
        #pragma unroll
        for (int no = 0; no < 8; no++) {
            float a = __fdiv_rn(__fmul_rn(pv[no], n), den);
            a1s[t*8+no] = __float2int_rn(__fmul_rn(a, 256.f));
        }
    }
    __syncthreads();

    // --- phase 1: x tile interior (pre-split halves, pure gathers) ---
    {
        const __half* xh = g_xh + blockIdx.x*2048;
        const __half* xl = g_xl + blockIdx.x*2048;
        unsigned short* dh = (unsigned short*)(sh + XSH_OFF);
        unsigned short* dl = (unsigned short*)(sh + XSL_OFF);
        #pragma unroll
        for (int i = 0; i < 4; i++) {
            int idx = t + i*512;
            int ni = idx >> 8, rem = idx & 255;
            int dsto = ni*324 + ((rem>>4)+1)*18 + (rem&15) + 1;
            dh[dsto] = __half_as_ushort(xh[idx]);
            dl[dsto] = __half_as_ushort(xl[idx]);
        }
    }
    __syncthreads();

    // --- phase 2: A build (im2col gather of pre-split halves) ---
    {
        const int p = t & 255;
        const unsigned short* xsrc = (unsigned short*)(sh + ((t < 256) ? XSH_OFF : XSL_OFF));
        char* dst = sh + ((t < 256) ? AHI_OFF : ALO_OFF) + p*ROWB;
        const int xyb = (p >> 4)*18 + (p & 15);
        #pragma unroll
        for (int q = 0; q < 9; q++) {
            uint32_t u[4];
            #pragma unroll
            for (int j = 0; j < 4; j++) {
                uint32_t v0 = xsrc[klut[q*8 + 2*j]     + xyb];
                uint32_t v1 = xsrc[klut[q*8 + 2*j + 1] + xyb];
                u[j] = v0 | (v1 << 16);
            }
            *(uint4*)(dst + q*16) = make_uint4(u[0], u[1], u[2], u[3]);
        }
        *(uint4*)(dst + 144) = make_uint4(0,0,0,0);
        *(uint4*)(dst + 160) = make_uint4(0,0,0,0);
    }
    __syncthreads();

    // --- MMA: warp w -> p-base (w&7)*32, o-quarter (w>>3)*128, 4 o-passes ---
    const int pbase = (wid & 7)*32;
    const int obase = (wid >> 3)*128;
    const int lane2 = (lane & 3)*2;

    #pragma unroll 1
    for (int pass = 0; pass < 4; pass++) {
        const int otile = obase + pass*32;
        float acc[2][4][4];
        #pragma unroll
        for (int mt = 0; mt < 2; mt++)
            #pragma unroll
            for (int nt = 0; nt < 4; nt++)
                #pragma unroll
                for (int j = 0; j < 4; j++) acc[mt][nt][j] = 0.f;

        #pragma unroll
        for (int kc = 0; kc < 5; kc++) {
            // A fragments (row-major [p][k])
            uint32_t ah[2][4], al[2][4];
            #pragma unroll
            for (int mt = 0; mt < 2; mt++) {
                const uint32_t arow = pbase + mt*16 + (lane & 15);
                const uint32_t aoff = arow*ROWB + kc*32 + ((lane >> 4) << 4);
                LDMX4(ah[mt][0], ah[mt][1], ah[mt][2], ah[mt][3], smb + AHI_OFF + aoff);
                LDMX4(al[mt][0], al[mt][1], al[mt][2], al[mt][3], smb + ALO_OFF + aoff);
            }
            // B fragments ([o][k] rows)
            uint32_t bh[4][2], bl[4][2];
            #pragma unroll
            for (int g = 0; g < 2; g++) {
                const uint32_t row = otile + g*16 + (lane & 7) + ((lane >> 4) << 3);
                const uint32_t koff = kc*32 + ((lane >> 3) & 1)*16;
                LDMX4(bh[2*g][0], bh[2*g][1], bh[2*g+1][0], bh[2*g+1][1],
                      smb + BHI_OFF + row*ROWB + koff);
                LDMX4(bl[2*g][0], bl[2*g][1], bl[2*g+1][0], bl[2*g+1][1],
                      smb + BLO_OFF + row*ROWB + koff);
            }
            if (kc < 4) {
                // product-major issue order: 8 independent MMAs per product
                #pragma unroll
                for (int mt = 0; mt < 2; mt++)
                    #pragma unroll
                    for (int nt = 0; nt < 4; nt++)
                        MMA16816(acc[mt][nt], ah[mt], bh[nt]);
                #pragma unroll
                for (int mt = 0; mt < 2; mt++)
                    #pragma unroll
                    for (int nt = 0; nt < 4; nt++)
                        MMA16816(acc[mt][nt], ah[mt], bl[nt]);
                #pragma unroll
                for (int mt = 0; mt < 2; mt++)
                    #pragma unroll
                    for (int nt = 0; nt < 4; nt++)
                        MMA16816(acc[mt][nt], al[mt], bh[nt]);
            } else {   // k 64..71 only: m16n8k8 (pad products would be exact zeros)
                #pragma unroll
                for (int mt = 0; mt < 2; mt++)
                    #pragma unroll
                    for (int nt = 0; nt < 4; nt++)
                        MMA1688(acc[mt][nt], ah[mt][0], ah[mt][1], bh[nt][0]);
                #pragma unroll
                for (int mt = 0; mt < 2; mt++)
                    #pragma unroll
                    for (int nt = 0; nt < 4; nt++)
                        MMA1688(acc[mt][nt], ah[mt][0], ah[mt][1], bl[nt][0]);
                #pragma unroll
                for (int mt = 0; mt < 2; mt++)
                    #pragma unroll
                    for (int nt = 0; nt < 4; nt++)
                        MMA1688(acc[mt][nt], al[mt][0], al[mt][1], bh[nt][0]);
            }
        }

        // --- epilogue: quant votes direct-to-global + quad-shuffle logit fold ---
        #pragma unroll
        for (int mt = 0; mt < 2; mt++) {
            const int p0 = pbase + mt*16 + (lane >> 2);
            #pragma unroll
            for (int nt = 0; nt < 4; nt++) {
                const int o = otile + nt*8 + lane2;     // even: o, o+1 share co
                const float cb0 = cbs[o], cb1 = cbs[o+1];
                int v0 = __float2int_rn((acc[mt][nt][0] + cb0) * 256.f);
                int v1 = __float2int_rn((acc[mt][nt][1] + cb1) * 256.f);
                int v2 = __float2int_rn((acc[mt][nt][2] + cb0) * 256.f);
                int v3 = __float2int_rn((acc[mt][nt][3] + cb1) * 256.f);
                short* vb = g_votes + ((size_t)b << 21) + (o >> 3)*65536
                          + ci*2048 + (o & 7)*256;
                vb[p0]           = (short)v0;
                vb[256 + p0]     = (short)v1;
                vb[p0 + 8]       = (short)v2;
                vb[256 + p0 + 8] = (short)v3;
                int s0 = a1s[o]*v0 + a1s[o+1]*v1;       // p0
                int s1 = a1s[o]*v2 + a1s[o+1]*v3;       // p0+8
                s0 += __shfl_xor_sync(0xffffffffu, s0, 1);
                s0 += __shfl_xor_sync(0xffffffffu, s0, 2);
                s1 += __shfl_xor_sync(0xffffffffu, s1, 1);
                s1 += __shfl_xor_sync(0xffffffffu, s1, 2);
                if ((lane & 3) == 0) {
                    const int co = o >> 3;
                    float* lb = g_logits + ((b*32 + ci)*32 + co)*256;
                    lb[p0]     = rintf((float)s0 * 0.00390625f) * 0.00390625f;
                    lb[p0 + 8] = rintf((float)s1 * 0.00390625f) * 0.00390625f;
                }
            }
        }
    }
}

// ---------------------------------------------------------------------------
// Kernel 2: softmax stats per (b, ci) over 8192 logits
// ---------------------------------------------------------------------------
__global__ void __launch_bounds__(256) softmax_kernel()
{
    const int row = blockIdx.x;
    const float* lp = g_logits + row*8192;
    const int t = threadIdx.x;
    float fl[32];
    #pragma unroll
    for (int i = 0; i < 32; i++) fl[i] = lp[i*256 + t];
    float m = fl[0];
    #pragma unroll
    for (int i = 1; i < 32; i++) m = fmaxf(m, fl[i]);
    __shared__ float red[8];
    #pragma unroll
    for (int off = 16; off; off >>= 1) m = fmaxf(m, __shfl_xor_sync(0xffffffffu, m, off));
    if ((t & 31) == 0) red[t >> 5] = m;
    __syncthreads();
    float M = red[0];
    #pragma unroll
    for (int i = 1; i < 8; i++) M = fmaxf(M, red[i]);
    __syncthreads();
    float s = 0.f;
    #pragma unroll
    for (int i = 0; i < 32; i++) s += expf(fl[i] - M);
    #pragma unroll
    for (int off = 16; off; off >>= 1) s += __shfl_xor_sync(0xffffffffu, s, off);
    if ((t & 31) == 0) red[t >> 5] = s;
    __syncthreads();
    if (t == 0) {
        float S = red[0];
        for (int i = 1; i < 8; i++) S += red[i];
        g_smax[row] = M;
        g_ssum[row] = S;
    }
}

// ---------------------------------------------------------------------------
// Kernel 3: fused routing iteration. block = (b, co, p-half); 128 threads.
// ---------------------------------------------------------------------------
__global__ void __launch_bounds__(128) route_kernel(
    const float* __restrict__ bias, float* __restrict__ out, int last)
{
    extern __shared__ char shb[];
    short* sv    = (short*)shb;                 // [32ci][8no][128p] = 65536 B
    float* smaxs = (float*)(shb + 65536);
    float* ssums = (float*)(shb + 65664);
    float* sb    = (float*)(shb + 65792);

    const int t   = threadIdx.x;
    const int blk = blockIdx.x;
    const int bco = blk >> 1, ph = blk & 1;
    const int b   = bco >> 5, co = bco & 31;

    {
        const short* src0 = g_votes + (size_t)bco*65536 + ph*128;
        uint4* dst = (uint4*)sv;
        #pragma unroll
        for (int r = 0; r < 32; r++) {
            int idx = r*128 + t;
            int cino = idx >> 4, ch = idx & 15;
            dst[idx] = *(const uint4*)(src0 + cino*256 + ch*8);
        }
    }
    if (t < 32) { smaxs[t] = g_smax[b*32 + t]; ssums[t] = g_ssum[b*32 + t]; }
    if (t < 8)  sb[t] = bias[co*8 + t];
    __syncthreads();

    float l[32];
    int S[8] = {0,0,0,0,0,0,0,0};
    const float* lgp = g_logits + (b*32)*8192 + co*256 + ph*128 + t;
    #pragma unroll
    for (int c = 0; c < 32; c++) {
        float lv = lgp[c*8192];
        l[c] = lv;
        float e = expf(lv - smaxs[c]);
        int r = __float2int_rn(__fmul_rn(__fdiv_rn(e, ssums[c]), 256.f));
        if (r) {
            #pragma unroll
            for (int no = 0; no < 8; no++)
                S[no] += r * (int)sv[(c*8 + no)*128 + t];
        }
    }
    float pq[8]; float ss = 0.f;
    #pragma unroll
    for (int no = 0; no < 8; no++) {
        float pre = __fadd_rn(__fmul_rn((float)S[no], 1.52587890625e-05f), sb[no]);
        float q = rintf(__fmul_rn(pre, 256.f)) * 0.00390625f;
        pq[no] = q; ss = __fadd_rn(ss, __fmul_rn(q, q));
    }
    float n   = sqrtf(ss);
    float den = __fadd_rn(1.f, __fmul_rn(n, n));
    int ai[8];
    #pragma unroll
    for (int no = 0; no < 8; no++) {
        float a = __fdiv_rn(__fmul_rn(pq[no], n), den);
        int q = __float2int_rn(__fmul_rn(a, 256.f));
        ai[no] = q;
        out[(bco*8 + no)*256 + ph*128 + t] = (float)q * 0.00390625f;
    }
    if (!last) {
        float* lw = g_logits + (b*32)*8192 + co*256 + ph*128 + t;
        #pragma unroll
        for (int c = 0; c < 32; c++) {
            int m = 0;
            #pragma unroll
            for (int no = 0; no < 8; no++)
                m += ai[no] * (int)sv[(c*8 + no)*128 + t];
            float lg = __fadd_rn(l[c], __fmul_rn((float)m, 1.52587890625e-05f));
            lw[c*8192] = rintf(__fmul_rn(lg, 256.f)) * 0.00390625f;
        }
    }
}

// ---------------------------------------------------------------------------
extern "C" void kernel_launch(void* const* d_in, const int* in_sizes, int n_in,
                              void* d_out, int out_size)
{
    const float* x    = (const float*)d_in[0];
    const float* w    = (const float*)d_in[1];
    const float* cb   = (const float*)d_in[2];
    const float* bias = (const float*)d_in[3];
    float* out = (float*)d_out;
    (void)in_sizes; (void)n_in; (void)out_size;

    const int ROUTE_SMEM = 65824;
    cudaFuncSetAttribute(conv_votes_kernel, cudaFuncAttributeMaxDynamicSharedMemorySize, CONV_SMEM);
    cudaFuncSetAttribute(route_kernel,      cudaFuncAttributeMaxDynamicSharedMemorySize, ROUTE_SMEM);

    prep_w_kernel<<<1, 256>>>(w);                             // launch 1
    prep_x_kernel<<<1024, 256>>>(x);                          // launch 2
    noop_kernel<<<1, 32>>>();                                 // launch 3
    conv_votes_kernel<<<1024, 512, CONV_SMEM>>>(cb, bias);    // launch 4 -> profiled
    softmax_kernel<<<1024, 256>>>();                          // iteration 2
    route_kernel<<<2048, 128, ROUTE_SMEM>>>(bias, out, 0);
    softmax_kernel<<<1024, 256>>>();                          // iteration 3
    route_kernel<<<2048, 128, ROUTE_SMEM>>>(bias, out, 1);
}

// round 11
// speedup vs baseline: 1.0921x; 1.0665x over previous
#include <cuda_runtime.h>
#include <cuda_fp16.h>
#include <cstdint>

#define BSZ 32
#define CIc 32
#define PP  256

__device__ short g_votes[BSZ*32*CIc*8*PP];   // [b][co][ci][p][no], value*256 (exact)
__device__ float g_logits[BSZ*CIc*32*PP];    // [b][ci][co][p]
__device__ float g_smax[BSZ*CIc];
__device__ float g_ssum[BSZ*CIc];
__device__ uint4  g_wsplit[5632];            // W fp16 hi[0..45056) lo[45056..90112), 176B rows
__device__ __half g_xh[BSZ*CIc*2048];        // x fp16 hi
__device__ __half g_xl[BSZ*CIc*2048];        // x fp16 lo

// ---------------- helpers ----------------
static __device__ __forceinline__ uint32_t smem_u32(const void* p) {
    uint32_t a;
    asm("{ .reg .u64 t; cvta.to.shared.u64 t, %1; cvt.u32.u64 %0, t; }" : "=r"(a) : "l"(p));
    return a;
}

#define MMA16816(d, a, b) \
    asm volatile("mma.sync.aligned.m16n8k16.row.col.f32.f16.f16.f32 " \
        "{%0,%1,%2,%3}, {%4,%5,%6,%7}, {%8,%9}, {%0,%1,%2,%3};" \
        : "+f"((d)[0]), "+f"((d)[1]), "+f"((d)[2]), "+f"((d)[3]) \
        : "r"((a)[0]), "r"((a)[1]), "r"((a)[2]), "r"((a)[3]), "r"((b)[0]), "r"((b)[1]))

#define MMA1688(d, a0, a1, b0) \
    asm volatile("mma.sync.aligned.m16n8k8.row.col.f32.f16.f16.f32 " \
        "{%0,%1,%2,%3}, {%4,%5}, {%6}, {%0,%1,%2,%3};" \
        : "+f"((d)[0]), "+f"((d)[1]), "+f"((d)[2]), "+f"((d)[3]) \
        : "r"(a0), "r"(a1), "r"(b0))

#define LDMX4(r0, r1, r2, r3, addr) \
    asm volatile("ldmatrix.sync.aligned.m8n8.x4.shared.b16 {%0,%1,%2,%3}, [%4];" \
        : "=r"(r0), "=r"(r1), "=r"(r2), "=r"(r3) : "r"(addr))

static __device__ __forceinline__ uint32_t packh(__half a, __half b) {
    return (uint32_t)__half_as_ushort(a) | ((uint32_t)__half_as_ushort(b) << 16);
}
static __device__ __forceinline__ uint32_t packsplit(float f0, float f1, uint32_t &lo) {
    __half h0 = __float2half_rn(f0), h1 = __float2half_rn(f1);
    __half l0 = __float2half_rn(__fsub_rn(f0, __half2float(h0)));
    __half l1 = __float2half_rn(__fsub_rn(f1, __half2float(h1)));
    lo = packh(l0, l1);
    return packh(h0, h1);
}
static __device__ __forceinline__ void upk(uint32_t u, int &a, int &b) {
    a = (int)(short)(u & 0xFFFFu);
    b = ((int)u) >> 16;
}

// 176B rows: 44*i mod 32 covers all banks -> ldmatrix conflict-free
#define ROWB       176u
#define BHI_OFF    0u
#define BLO_OFF    45056u
#define AHI_OFF    90112u
#define ALO_OFF    135168u
#define XSH_OFF    180224u
#define XSL_OFF    185408u
#define CBS_OFF    190592u
#define A1S_OFF    191616u
#define KLUT_OFF   192640u
#define CONV_SMEM  192928

// ---------------------------------------------------------------------------
// Prep: x -> fp16 hi/lo per tile; block 0 additionally splits W (layout-final)
// ---------------------------------------------------------------------------
__global__ void __launch_bounds__(256) prep_kernel(
    const float* __restrict__ x, const float* __restrict__ w)
{
    const int tile = blockIdx.x;           // b*32 + ci
    const float4* src = (const float4*)(x + tile*2048);
    #pragma unroll
    for (int i = 0; i < 2; i++) {
        int idx4 = threadIdx.x + i*256;
        float4 v = src[idx4];
        uint32_t l0, l1;
        uint32_t h0 = packsplit(v.x, v.y, l0);
        uint32_t h1 = packsplit(v.z, v.w, l1);
        *(uint2*)(g_xh + tile*2048 + idx4*4) = make_uint2(h0, h1);
        *(uint2*)(g_xl + tile*2048 + idx4*4) = make_uint2(l0, l1);
    }
    if (blockIdx.x == 0) {
        const int o = threadIdx.x;
        const float4* wr = (const float4*)(w + o*72);
        char* bh = (char*)g_wsplit + o*ROWB;
        char* bl = (char*)g_wsplit + 45056 + o*ROWB;
        #pragma unroll
        for (int q = 0; q < 18; q++) {
            float4 v = wr[q];
            uint32_t l0, l1;
            uint32_t h0 = packsplit(v.x, v.y, l0);
            uint32_t h1 = packsplit(v.z, v.w, l1);
            *(uint2*)(bh + q*8) = make_uint2(h0, h1);
            *(uint2*)(bl + q*8) = make_uint2(l0, l1);
        }
        *(uint4*)(bh + 144) = make_uint4(0,0,0,0);
        *(uint4*)(bh + 160) = make_uint4(0,0,0,0);
        *(uint4*)(bl + 144) = make_uint4(0,0,0,0);
        *(uint4*)(bl + 160) = make_uint4(0,0,0,0);
    }
}

// ---------------------------------------------------------------------------
// Kernel 1: fp16-split mma.sync conv -> int16 votes + iteration-1 logits.
// block = (b, ci), 512 threads / 16 warps. Votes now [b][co][ci][p][no].
// ---------------------------------------------------------------------------
__global__ void __launch_bounds__(512, 1) conv_votes_kernel(
    const float* __restrict__ cb, const float* __restrict__ bias)
{
    extern __shared__ char sh[];
    float* cbs = (float*)(sh + CBS_OFF);
    int*   a1s = (int*)(sh + A1S_OFF);
    int*   klut= (int*)(sh + KLUT_OFF);
    const uint32_t smb = smem_u32(sh);

    const int t = threadIdx.x;
    const int wid = t >> 5, lane = t & 31;
    const int b = blockIdx.x >> 5, ci = blockIdx.x & 31;

    {
        const uint4* src = g_wsplit;
        uint4* dst = (uint4*)sh;
        #pragma unroll
        for (int i = 0; i < 11; i++) dst[t + i*512] = src[t + i*512];
    }
    {
        uint32_t* z = (uint32_t*)(sh + XSH_OFF);
        #pragma unroll
        for (int i = 0; i < 6; i++) {
            int idx = t + i*512;
            if (idx < 2592) z[idx] = 0;
        }
    }
    if (t < 256) cbs[t] = cb[t];
    if (t < 72) { int ni = t/9, r = t%9; klut[t] = ni*324 + (r/3)*18 + (r%3); }
    if (t < 32) {
        float pv[8]; float ss = 0.f;
        #pragma unroll
        for (int no = 0; no < 8; no++) {
            float q = rintf(__fmul_rn(bias[t*8+no], 256.f)) * 0.00390625f;
            pv[no] = q; ss = __fadd_rn(ss, __fmul_rn(q, q));
        }
        float n = sqrtf(ss);
        float den = __fadd_rn(1.f, __fmul_rn(n, n));
        #pragma unroll
        for (int no = 0; no < 8; no++) {
            float a = __fdiv_rn(__fmul_rn(pv[no], n), den);
            a1s[t*8+no] = __float2int_rn(__fmul_rn(a, 256.f));
        }
    }
    __syncthreads();

    {
        const __half* xh = g_xh + blockIdx.x*2048;
        const __half* xl = g_xl + blockIdx.x*2048;
        unsigned short* dh = (unsigned short*)(sh + XSH_OFF);
        unsigned short* dl = (unsigned short*)(sh + XSL_OFF);
        #pragma unroll
        for (int i = 0; i < 4; i++) {
            int idx = t + i*512;
            int ni = idx >> 8, rem = idx & 255;
            int dsto = ni*324 + ((rem>>4)+1)*18 + (rem&15) + 1;
            dh[dsto] = __half_as_ushort(xh[idx]);
            dl[dsto] = __half_as_ushort(xl[idx]);
        }
    }
    __syncthreads();
    {
        const int p = t & 255;
        const unsigned short* xsrc = (unsigned short*)(sh + ((t < 256) ? XSH_OFF : XSL_OFF));
        char* dst = sh + ((t < 256) ? AHI_OFF : ALO_OFF) + p*ROWB;
        const int xyb = (p >> 4)*18 + (p & 15);
        #pragma unroll
        for (int q = 0; q < 9; q++) {
            uint32_t u[4];
            #pragma unroll
            for (int j = 0; j < 4; j++) {
                uint32_t v0 = xsrc[klut[q*8 + 2*j]     + xyb];
                uint32_t v1 = xsrc[klut[q*8 + 2*j + 1] + xyb];
                u[j] = v0 | (v1 << 16);
            }
            *(uint4*)(dst + q*16) = make_uint4(u[0], u[1], u[2], u[3]);
        }
        *(uint4*)(dst + 144) = make_uint4(0,0,0,0);
        *(uint4*)(dst + 160) = make_uint4(0,0,0,0);
    }
    __syncthreads();

    const int pbase = (wid & 7)*32;
    const int obase = (wid >> 3)*128;
    const int lane2 = (lane & 3)*2;

    #pragma unroll 1
    for (int pass = 0; pass < 4; pass++) {
        const int otile = obase + pass*32;
        float acc[2][4][4];
        #pragma unroll
        for (int mt = 0; mt < 2; mt++)
            #pragma unroll
            for (int nt = 0; nt < 4; nt++)
                #pragma unroll
                for (int j = 0; j < 4; j++) acc[mt][nt][j] = 0.f;

        #pragma unroll
        for (int kc = 0; kc < 5; kc++) {
            uint32_t ah[2][4], al[2][4];
            #pragma unroll
            for (int mt = 0; mt < 2; mt++) {
                const uint32_t arow = pbase + mt*16 + (lane & 15);
                const uint32_t aoff = arow*ROWB + kc*32 + ((lane >> 4) << 4);
                LDMX4(ah[mt][0], ah[mt][1], ah[mt][2], ah[mt][3], smb + AHI_OFF + aoff);
                LDMX4(al[mt][0], al[mt][1], al[mt][2], al[mt][3], smb + ALO_OFF + aoff);
            }
            uint32_t bh[4][2], bl[4][2];
            #pragma unroll
            for (int g = 0; g < 2; g++) {
                const uint32_t row = otile + g*16 + (lane & 7) + ((lane >> 4) << 3);
                const uint32_t koff = kc*32 + ((lane >> 3) & 1)*16;
                LDMX4(bh[2*g][0], bh[2*g][1], bh[2*g+1][0], bh[2*g+1][1],
                      smb + BHI_OFF + row*ROWB + koff);
                LDMX4(bl[2*g][0], bl[2*g][1], bl[2*g+1][0], bl[2*g+1][1],
                      smb + BLO_OFF + row*ROWB + koff);
            }
            if (kc < 4) {
                #pragma unroll
                for (int mt = 0; mt < 2; mt++)
                    #pragma unroll
                    for (int nt = 0; nt < 4; nt++)
                        MMA16816(acc[mt][nt], ah[mt], bh[nt]);
                #pragma unroll
                for (int mt = 0; mt < 2; mt++)
                    #pragma unroll
                    for (int nt = 0; nt < 4; nt++)
                        MMA16816(acc[mt][nt], ah[mt], bl[nt]);
                #pragma unroll
                for (int mt = 0; mt < 2; mt++)
                    #pragma unroll
                    for (int nt = 0; nt < 4; nt++)
                        MMA16816(acc[mt][nt], al[mt], bh[nt]);
            } else {
                #pragma unroll
                for (int mt = 0; mt < 2; mt++)
                    #pragma unroll
                    for (int nt = 0; nt < 4; nt++)
                        MMA1688(acc[mt][nt], ah[mt][0], ah[mt][1], bh[nt][0]);
                #pragma unroll
                for (int mt = 0; mt < 2; mt++)
                    #pragma unroll
                    for (int nt = 0; nt < 4; nt++)
                        MMA1688(acc[mt][nt], ah[mt][0], ah[mt][1], bl[nt][0]);
                #pragma unroll
                for (int mt = 0; mt < 2; mt++)
                    #pragma unroll
                    for (int nt = 0; nt < 4; nt++)
                        MMA1688(acc[mt][nt], al[mt][0], al[mt][1], bh[nt][0]);
            }
        }

        // epilogue: votes [ci][p][no] (u32 pair stores) + quad-shuffle logit fold
        #pragma unroll
        for (int mt = 0; mt < 2; mt++) {
            const int p0 = pbase + mt*16 + (lane >> 2);
            #pragma unroll
            for (int nt = 0; nt < 4; nt++) {
                const int o = otile + nt*8 + lane2;     // no = lane2 (even), co = o>>3
                const float cb0 = cbs[o], cb1 = cbs[o+1];
                int v0 = __float2int_rn((acc[mt][nt][0] + cb0) * 256.f);
                int v1 = __float2int_rn((acc[mt][nt][1] + cb1) * 256.f);
                int v2 = __float2int_rn((acc[mt][nt][2] + cb0) * 256.f);
                int v3 = __float2int_rn((acc[mt][nt][3] + cb1) * 256.f);
                short* vb = g_votes + ((size_t)b << 21) + ((o >> 3)*32 + ci)*2048;
                *(uint32_t*)(vb + p0*8 + lane2)       = (v0 & 0xFFFF) | ((uint32_t)v1 << 16);
                *(uint32_t*)(vb + (p0 + 8)*8 + lane2) = (v2 & 0xFFFF) | ((uint32_t)v3 << 16);
                int s0 = a1s[o]*v0 + a1s[o+1]*v1;
                int s1 = a1s[o]*v2 + a1s[o+1]*v3;
                s0 += __shfl_xor_sync(0xffffffffu, s0, 1);
                s0 += __shfl_xor_sync(0xffffffffu, s0, 2);
                s1 += __shfl_xor_sync(0xffffffffu, s1, 1);
                s1 += __shfl_xor_sync(0xffffffffu, s1, 2);
                if ((lane & 3) == 0) {
                    float* lb = g_logits + ((b*32 + ci)*32 + (o >> 3))*256;
                    lb[p0]     = rintf((float)s0 * 0.00390625f) * 0.00390625f;
                    lb[p0 + 8] = rintf((float)s1 * 0.00390625f) * 0.00390625f;
                }
            }
        }
    }
}

// ---------------------------------------------------------------------------
// Kernel 2: softmax stats per (b, ci) over 8192 logits
// ---------------------------------------------------------------------------
__global__ void __launch_bounds__(256) softmax_kernel()
{
    const int row = blockIdx.x;
    const float* lp = g_logits + row*8192;
    const int t = threadIdx.x;
    float fl[32];
    #pragma unroll
    for (int i = 0; i < 32; i++) fl[i] = lp[i*256 + t];
    float m = fl[0];
    #pragma unroll
    for (int i = 1; i < 32; i++) m = fmaxf(m, fl[i]);
    __shared__ float red[8];
    #pragma unroll
    for (int off = 16; off; off >>= 1) m = fmaxf(m, __shfl_xor_sync(0xffffffffu, m, off));
    if ((t & 31) == 0) red[t >> 5] = m;
    __syncthreads();
    float M = red[0];
    #pragma unroll
    for (int i = 1; i < 8; i++) M = fmaxf(M, red[i]);
    __syncthreads();
    float s = 0.f;
    #pragma unroll
    for (int i = 0; i < 32; i++) s += expf(fl[i] - M);
    #pragma unroll
    for (int off = 16; off; off >>= 1) s += __shfl_xor_sync(0xffffffffu, s, off);
    if ((t & 31) == 0) red[t >> 5] = s;
    __syncthreads();
    if (t == 0) {
        float S = red[0];
        for (int i = 1; i < 8; i++) S += red[i];
        g_smax[row] = M;
        g_ssum[row] = S;
    }
}

// ---------------------------------------------------------------------------
// Kernel 3: fused routing iteration. block = (b, co, p-half); 128 threads.
// Votes [ci][p][no]: one LDS.128 fetches all 8 no values per (c, p).
// ---------------------------------------------------------------------------
__global__ void __launch_bounds__(128) route_kernel(
    const float* __restrict__ bias, float* __restrict__ out, int last)
{
    extern __shared__ char shb[];
    uint32_t* sv = (uint32_t*)shb;              // [32ci][128p][8no] shorts = 64KB
    float* smaxs = (float*)(shb + 65536);
    float* ssums = (float*)(shb + 65664);
    float* sb    = (float*)(shb + 65792);

    const int t   = threadIdx.x;
    const int blk = blockIdx.x;
    const int bco = blk >> 1, ph = blk & 1;
    const int b   = bco >> 5, co = bco & 31;

    {   // staging: straight coalesced copy (per ci: 128 uint4 for this p-half)
        const uint4* src = (const uint4*)(g_votes + (size_t)bco*65536) + ph*128;
        uint4* dst = (uint4*)sv;
        #pragma unroll
        for (int ci = 0; ci < 32; ci++)
            dst[ci*128 + t] = src[ci*256 + t];
    }
    if (t < 32) { smaxs[t] = g_smax[b*32 + t]; ssums[t] = g_ssum[b*32 + t]; }
    if (t < 8)  sb[t] = bias[co*8 + t];
    __syncthreads();

    float l[32];
    int S[8] = {0,0,0,0,0,0,0,0};
    const float* lgp = g_logits + (b*32)*8192 + co*256 + ph*128 + t;
    #pragma unroll
    for (int c = 0; c < 32; c++) {
        float lv = lgp[c*8192];
        l[c] = lv;
        float e = expf(lv - smaxs[c]);
        int r = __float2int_rn(__fmul_rn(__fdiv_rn(e, ssums[c]), 256.f));
        if (r) {
            uint4 vv = *(const uint4*)(sv + c*512 + t*4);
            int e0, e1;
            upk(vv.x, e0, e1); S[0] += r*e0; S[1] += r*e1;
            upk(vv.y, e0, e1); S[2] += r*e0; S[3] += r*e1;
            upk(vv.z, e0, e1); S[4] += r*e0; S[5] += r*e1;
            upk(vv.w, e0, e1); S[6] += r*e0; S[7] += r*e1;
        }
    }
    float pq[8]; float ss = 0.f;
    #pragma unroll
    for (int no = 0; no < 8; no++) {
        float pre = __fadd_rn(__fmul_rn((float)S[no], 1.52587890625e-05f), sb[no]);
        float q = rintf(__fmul_rn(pre, 256.f)) * 0.00390625f;
        pq[no] = q; ss = __fadd_rn(ss, __fmul_rn(q, q));
    }
    float n   = sqrtf(ss);
    float den = __fadd_rn(1.f, __fmul_rn(n, n));
    int ai[8];
    #pragma unroll
    for (int no = 0; no < 8; no++) {
        float a = __fdiv_rn(__fmul_rn(pq[no], n), den);
        int q = __float2int_rn(__fmul_rn(a, 256.f));
        ai[no] = q;
        out[(bco*8 + no)*256 + ph*128 + t] = (float)q * 0.00390625f;
    }
    if (!last) {
        float* lw = g_logits + (b*32)*8192 + co*256 + ph*128 + t;
        #pragma unroll
        for (int c = 0; c < 32; c++) {
            uint4 vv = *(const uint4*)(sv + c*512 + t*4);
            int e0, e1, m = 0;
            upk(vv.x, e0, e1); m += ai[0]*e0 + ai[1]*e1;
            upk(vv.y, e0, e1); m += ai[2]*e0 + ai[3]*e1;
            upk(vv.z, e0, e1); m += ai[4]*e0 + ai[5]*e1;
            upk(vv.w, e0, e1); m += ai[6]*e0 + ai[7]*e1;
            float lg = __fadd_rn(l[c], __fmul_rn((float)m, 1.52587890625e-05f));
            lw[c*8192] = rintf(__fmul_rn(lg, 256.f)) * 0.00390625f;
        }
    }
}

// ---------------------------------------------------------------------------
extern "C" void kernel_launch(void* const* d_in, const int* in_sizes, int n_in,
                              void* d_out, int out_size)
{
    const float* x    = (const float*)d_in[0];
    const float* w    = (const float*)d_in[1];
    const float* cb   = (const float*)d_in[2];
    const float* bias = (const float*)d_in[3];
    float* out = (float*)d_out;
    (void)in_sizes; (void)n_in; (void)out_size;

    const int ROUTE_SMEM = 65824;
    cudaFuncSetAttribute(conv_votes_kernel, cudaFuncAttributeMaxDynamicSharedMemorySize, CONV_SMEM);
    cudaFuncSetAttribute(route_kernel,      cudaFuncAttributeMaxDynamicSharedMemorySize, ROUTE_SMEM);

    prep_kernel<<<1024, 256>>>(x, w);                         // launch 1 (W + x split)
    conv_votes_kernel<<<1024, 512, CONV_SMEM>>>(cb, bias);    // launch 2 (+ iter 1 folded)
    softmax_kernel<<<1024, 256>>>();                          // launch 3 (iteration 2)
    route_kernel<<<2048, 128, ROUTE_SMEM>>>(bias, out, 0);    // launch 4 -> profiled
    softmax_kernel<<<1024, 256>>>();                          // iteration 3
    route_kernel<<<2048, 128, ROUTE_SMEM>>>(bias, out, 1);
}

// round 12
// speedup vs baseline: 1.5757x; 1.4429x over previous
#include <cuda_runtime.h>
#include <cuda_fp16.h>
#include <cstdint>

#define BSZ 32
#define CIc 32
#define PP  256

__device__ short g_votes[BSZ*32*CIc*8*PP];   // [b][co][ci][p][no], value*256 (exact)
__device__ float g_logits[BSZ*CIc*32*PP];    // [b][ci][co][p]
__device__ float g_smax[BSZ*CIc];
__device__ float g_ssum[BSZ*CIc];
__device__ uint4  g_wsplit[5632];            // W fp16 hi[0..45056) lo[45056..90112), 176B rows
__device__ __half g_xh[BSZ*CIc*2048];        // x fp16 hi
__device__ __half g_xl[BSZ*CIc*2048];        // x fp16 lo

// ---------------- helpers ----------------
static __device__ __forceinline__ uint32_t smem_u32(const void* p) {
    uint32_t a;
    asm("{ .reg .u64 t; cvta.to.shared.u64 t, %1; cvt.u32.u64 %0, t; }" : "=r"(a) : "l"(p));
    return a;
}

#define MMA16816(d, a, b) \
    asm volatile("mma.sync.aligned.m16n8k16.row.col.f32.f16.f16.f32 " \
        "{%0,%1,%2,%3}, {%4,%5,%6,%7}, {%8,%9}, {%0,%1,%2,%3};" \
        : "+f"((d)[0]), "+f"((d)[1]), "+f"((d)[2]), "+f"((d)[3]) \
        : "r"((a)[0]), "r"((a)[1]), "r"((a)[2]), "r"((a)[3]), "r"((b)[0]), "r"((b)[1]))

#define MMA1688(d, a0, a1, b0) \
    asm volatile("mma.sync.aligned.m16n8k8.row.col.f32.f16.f16.f32 " \
        "{%0,%1,%2,%3}, {%4,%5}, {%6}, {%0,%1,%2,%3};" \
        : "+f"((d)[0]), "+f"((d)[1]), "+f"((d)[2]), "+f"((d)[3]) \
        : "r"(a0), "r"(a1), "r"(b0))

#define LDMX4(r0, r1, r2, r3, addr) \
    asm volatile("ldmatrix.sync.aligned.m8n8.x4.shared.b16 {%0,%1,%2,%3}, [%4];" \
        : "=r"(r0), "=r"(r1), "=r"(r2), "=r"(r3) : "r"(addr))

static __device__ __forceinline__ uint32_t packh(__half a, __half b) {
    return (uint32_t)__half_as_ushort(a) | ((uint32_t)__half_as_ushort(b) << 16);
}
static __device__ __forceinline__ uint32_t packsplit(float f0, float f1, uint32_t &lo) {
    __half h0 = __float2half_rn(f0), h1 = __float2half_rn(f1);
    __half l0 = __float2half_rn(__fsub_rn(f0, __half2float(h0)));
    __half l1 = __float2half_rn(__fsub_rn(f1, __half2float(h1)));
    lo = packh(l0, l1);
    return packh(h0, h1);
}
static __device__ __forceinline__ void upk(uint32_t u, int &a, int &b) {
    a = (int)(short)(u & 0xFFFFu);
    b = ((int)u) >> 16;
}

// 176B rows: 44*i mod 32 covers all banks -> ldmatrix conflict-free
#define ROWB       176u
#define BHI_OFF    0u
#define BLO_OFF    45056u
#define AHI_OFF    90112u
#define ALO_OFF    135168u
#define XSH_OFF    180224u
#define XSL_OFF    185408u
#define CBS_OFF    190592u
#define A1S_OFF    191616u
#define KLUT_OFF   192640u
#define CONV_SMEM  192928

// ---------------------------------------------------------------------------
// Prep: x -> fp16 hi/lo per tile; block 0 additionally splits W (layout-final)
// ---------------------------------------------------------------------------
__global__ void __launch_bounds__(256) prep_kernel(
    const float* __restrict__ x, const float* __restrict__ w)
{
    const int tile = blockIdx.x;           // b*32 + ci
    const float4* src = (const float4*)(x + tile*2048);
    #pragma unroll
    for (int i = 0; i < 2; i++) {
        int idx4 = threadIdx.x + i*256;
        float4 v = src[idx4];
        uint32_t l0, l1;
        uint32_t h0 = packsplit(v.x, v.y, l0);
        uint32_t h1 = packsplit(v.z, v.w, l1);
        *(uint2*)(g_xh + tile*2048 + idx4*4) = make_uint2(h0, h1);
        *(uint2*)(g_xl + tile*2048 + idx4*4) = make_uint2(l0, l1);
    }
    if (blockIdx.x == 0) {
        const int o = threadIdx.x;
        const float4* wr = (const float4*)(w + o*72);
        char* bh = (char*)g_wsplit + o*ROWB;
        char* bl = (char*)g_wsplit + 45056 + o*ROWB;
        #pragma unroll
        for (int q = 0; q < 18; q++) {
            float4 v = wr[q];
            uint32_t l0, l1;
            uint32_t h0 = packsplit(v.x, v.y, l0);
            uint32_t h1 = packsplit(v.z, v.w, l1);
            *(uint2*)(bh + q*8) = make_uint2(h0, h1);
            *(uint2*)(bl + q*8) = make_uint2(l0, l1);
        }
        *(uint4*)(bh + 144) = make_uint4(0,0,0,0);
        *(uint4*)(bh + 160) = make_uint4(0,0,0,0);
        *(uint4*)(bl + 144) = make_uint4(0,0,0,0);
        *(uint4*)(bl + 160) = make_uint4(0,0,0,0);
    }
}

// ---------------------------------------------------------------------------
// Kernel 1: fp16-split mma.sync conv -> int16 votes + iteration-1 logits.
// block = (b, ci), 512 threads / 16 warps. Votes [b][co][ci][p][no].
// ---------------------------------------------------------------------------
__global__ void __launch_bounds__(512, 1) conv_votes_kernel(
    const float* __restrict__ cb, const float* __restrict__ bias)
{
    extern __shared__ char sh[];
    float* cbs = (float*)(sh + CBS_OFF);
    int*   a1s = (int*)(sh + A1S_OFF);
    int*   klut= (int*)(sh + KLUT_OFF);
    const uint32_t smb = smem_u32(sh);

    const int t = threadIdx.x;
    const int wid = t >> 5, lane = t & 31;
    const int b = blockIdx.x >> 5, ci = blockIdx.x & 31;

    {
        const uint4* src = g_wsplit;
        uint4* dst = (uint4*)sh;
        #pragma unroll
        for (int i = 0; i < 11; i++) dst[t + i*512] = src[t + i*512];
    }
    {
        uint32_t* z = (uint32_t*)(sh + XSH_OFF);
        #pragma unroll
        for (int i = 0; i < 6; i++) {
            int idx = t + i*512;
            if (idx < 2592) z[idx] = 0;
        }
    }
    if (t < 256) cbs[t] = cb[t];
    if (t < 72) { int ni = t/9, r = t%9; klut[t] = ni*324 + (r/3)*18 + (r%3); }
    if (t < 32) {
        float pv[8]; float ss = 0.f;
        #pragma unroll
        for (int no = 0; no < 8; no++) {
            float q = rintf(__fmul_rn(bias[t*8+no], 256.f)) * 0.00390625f;
            pv[no] = q; ss = __fadd_rn(ss, __fmul_rn(q, q));
        }
        float n = sqrtf(ss);
        float den = __fadd_rn(1.f, __fmul_rn(n, n));
        #pragma unroll
        for (int no = 0; no < 8; no++) {
            float a = __fdiv_rn(__fmul_rn(pv[no], n), den);
            a1s[t*8+no] = __float2int_rn(__fmul_rn(a, 256.f));
        }
    }
    __syncthreads();

    {
        const __half* xh = g_xh + blockIdx.x*2048;
        const __half* xl = g_xl + blockIdx.x*2048;
        unsigned short* dh = (unsigned short*)(sh + XSH_OFF);
        unsigned short* dl = (unsigned short*)(sh + XSL_OFF);
        #pragma unroll
        for (int i = 0; i < 4; i++) {
            int idx = t + i*512;
            int ni = idx >> 8, rem = idx & 255;
            int dsto = ni*324 + ((rem>>4)+1)*18 + (rem&15) + 1;
            dh[dsto] = __half_as_ushort(xh[idx]);
            dl[dsto] = __half_as_ushort(xl[idx]);
        }
    }
    __syncthreads();
    {
        const int p = t & 255;
        const unsigned short* xsrc = (unsigned short*)(sh + ((t < 256) ? XSH_OFF : XSL_OFF));
        char* dst = sh + ((t < 256) ? AHI_OFF : ALO_OFF) + p*ROWB;
        const int xyb = (p >> 4)*18 + (p & 15);
        #pragma unroll
        for (int q = 0; q < 9; q++) {
            uint32_t u[4];
            #pragma unroll
            for (int j = 0; j < 4; j++) {
                uint32_t v0 = xsrc[klut[q*8 + 2*j]     + xyb];
                uint32_t v1 = xsrc[klut[q*8 + 2*j + 1] + xyb];
                u[j] = v0 | (v1 << 16);
            }
            *(uint4*)(dst + q*16) = make_uint4(u[0], u[1], u[2], u[3]);
        }
        *(uint4*)(dst + 144) = make_uint4(0,0,0,0);
        *(uint4*)(dst + 160) = make_uint4(0,0,0,0);
    }
    __syncthreads();

    const int pbase = (wid & 7)*32;
    const int obase = (wid >> 3)*128;
    const int lane2 = (lane & 3)*2;

    #pragma unroll 1
    for (int pass = 0; pass < 4; pass++) {
        const int otile = obase + pass*32;
        float acc[2][4][4];
        #pragma unroll
        for (int mt = 0; mt < 2; mt++)
            #pragma unroll
            for (int nt = 0; nt < 4; nt++)
                #pragma unroll
                for (int j = 0; j < 4; j++) acc[mt][nt][j] = 0.f;

        #pragma unroll
        for (int kc = 0; kc < 5; kc++) {
            uint32_t ah[2][4], al[2][4];
            #pragma unroll
            for (int mt = 0; mt < 2; mt++) {
                const uint32_t arow = pbase + mt*16 + (lane & 15);
                const uint32_t aoff = arow*ROWB + kc*32 + ((lane >> 4) << 4);
                LDMX4(ah[mt][0], ah[mt][1], ah[mt][2], ah[mt][3], smb + AHI_OFF + aoff);
                LDMX4(al[mt][0], al[mt][1], al[mt][2], al[mt][3], smb + ALO_OFF + aoff);
            }
            uint32_t bh[4][2], bl[4][2];
            #pragma unroll
            for (int g = 0; g < 2; g++) {
                const uint32_t row = otile + g*16 + (lane & 7) + ((lane >> 4) << 3);
                const uint32_t koff = kc*32 + ((lane >> 3) & 1)*16;
                LDMX4(bh[2*g][0], bh[2*g][1], bh[2*g+1][0], bh[2*g+1][1],
                      smb + BHI_OFF + row*ROWB + koff);
                LDMX4(bl[2*g][0], bl[2*g][1], bl[2*g+1][0], bl[2*g+1][1],
                      smb + BLO_OFF + row*ROWB + koff);
            }
            if (kc < 4) {
                #pragma unroll
                for (int mt = 0; mt < 2; mt++)
                    #pragma unroll
                    for (int nt = 0; nt < 4; nt++)
                        MMA16816(acc[mt][nt], ah[mt], bh[nt]);
                #pragma unroll
                for (int mt = 0; mt < 2; mt++)
                    #pragma unroll
                    for (int nt = 0; nt < 4; nt++)
                        MMA16816(acc[mt][nt], ah[mt], bl[nt]);
                #pragma unroll
                for (int mt = 0; mt < 2; mt++)
                    #pragma unroll
                    for (int nt = 0; nt < 4; nt++)
                        MMA16816(acc[mt][nt], al[mt], bh[nt]);
            } else {
                #pragma unroll
                for (int mt = 0; mt < 2; mt++)
                    #pragma unroll
                    for (int nt = 0; nt < 4; nt++)
                        MMA1688(acc[mt][nt], ah[mt][0], ah[mt][1], bh[nt][0]);
                #pragma unroll
                for (int mt = 0; mt < 2; mt++)
                    #pragma unroll
                    for (int nt = 0; nt < 4; nt++)
                        MMA1688(acc[mt][nt], ah[mt][0], ah[mt][1], bl[nt][0]);
                #pragma unroll
                for (int mt = 0; mt < 2; mt++)
                    #pragma unroll
                    for (int nt = 0; nt < 4; nt++)
                        MMA1688(acc[mt][nt], al[mt][0], al[mt][1], bh[nt][0]);
            }
        }

        // epilogue: votes [ci][p][no] (u32 pair stores) + quad-shuffle logit fold
        #pragma unroll
        for (int mt = 0; mt < 2; mt++) {
            const int p0 = pbase + mt*16 + (lane >> 2);
            #pragma unroll
            for (int nt = 0; nt < 4; nt++) {
                const int o = otile + nt*8 + lane2;     // no = lane2 (even), co = o>>3
                const float cb0 = cbs[o], cb1 = cbs[o+1];
                int v0 = __float2int_rn((acc[mt][nt][0] + cb0) * 256.f);
                int v1 = __float2int_rn((acc[mt][nt][1] + cb1) * 256.f);
                int v2 = __float2int_rn((acc[mt][nt][2] + cb0) * 256.f);
                int v3 = __float2int_rn((acc[mt][nt][3] + cb1) * 256.f);
                short* vb = g_votes + ((size_t)b << 21) + ((o >> 3)*32 + ci)*2048;
                *(uint32_t*)(vb + p0*8 + lane2)       = (v0 & 0xFFFF) | ((uint32_t)v1 << 16);
                *(uint32_t*)(vb + (p0 + 8)*8 + lane2) = (v2 & 0xFFFF) | ((uint32_t)v3 << 16);
                int s0 = a1s[o]*v0 + a1s[o+1]*v1;
                int s1 = a1s[o]*v2 + a1s[o+1]*v3;
                s0 += __shfl_xor_sync(0xffffffffu, s0, 1);
                s0 += __shfl_xor_sync(0xffffffffu, s0, 2);
                s1 += __shfl_xor_sync(0xffffffffu, s1, 1);
                s1 += __shfl_xor_sync(0xffffffffu, s1, 2);
                if ((lane & 3) == 0) {
                    float* lb = g_logits + ((b*32 + ci)*32 + (o >> 3))*256;
                    lb[p0]     = rintf((float)s0 * 0.00390625f) * 0.00390625f;
                    lb[p0 + 8] = rintf((float)s1 * 0.00390625f) * 0.00390625f;
                }
            }
        }
    }
}

// ---------------------------------------------------------------------------
// Kernel 2: softmax stats per (b, ci) over 8192 logits
// ---------------------------------------------------------------------------
__global__ void __launch_bounds__(256) softmax_kernel()
{
    const int row = blockIdx.x;
    const float* lp = g_logits + row*8192;
    const int t = threadIdx.x;
    float fl[32];
    #pragma unroll
    for (int i = 0; i < 32; i++) fl[i] = lp[i*256 + t];
    float m = fl[0];
    #pragma unroll
    for (int i = 1; i < 32; i++) m = fmaxf(m, fl[i]);
    __shared__ float red[8];
    #pragma unroll
    for (int off = 16; off; off >>= 1) m = fmaxf(m, __shfl_xor_sync(0xffffffffu, m, off));
    if ((t & 31) == 0) red[t >> 5] = m;
    __syncthreads();
    float M = red[0];
    #pragma unroll
    for (int i = 1; i < 8; i++) M = fmaxf(M, red[i]);
    __syncthreads();
    float s = 0.f;
    #pragma unroll
    for (int i = 0; i < 32; i++) s += expf(fl[i] - M);
    #pragma unroll
    for (int off = 16; off; off >>= 1) s += __shfl_xor_sync(0xffffffffu, s, off);
    if ((t & 31) == 0) red[t >> 5] = s;
    __syncthreads();
    if (t == 0) {
        float S = red[0];
        for (int i = 1; i < 8; i++) S += red[i];
        g_smax[row] = M;
        g_ssum[row] = S;
    }
}

// ---------------------------------------------------------------------------
// Kernel 3: fused routing iteration. block = (b, co, p-half); 128 threads.
// No smem vote staging: votes read straight from global (coalesced uint4),
// twice. smem ~300B -> 8 CTAs/SM (reg-capped), 32 warps for latency hiding.
// ---------------------------------------------------------------------------
__global__ void __launch_bounds__(128) route_kernel(
    const float* __restrict__ bias, float* __restrict__ out, int last)
{
    __shared__ float smaxs[32], ssums[32], sb[8];

    const int t   = threadIdx.x;
    const int blk = blockIdx.x;
    const int bco = blk >> 1, ph = blk & 1;
    const int b   = bco >> 5, co = bco & 31;

    if (t < 32) { smaxs[t] = g_smax[b*32 + t]; ssums[t] = g_ssum[b*32 + t]; }
    if (t < 8)  sb[t] = bias[co*8 + t];
    __syncthreads();

    // per-c vote vector: uint4 at [bco][c][p][*], coalesced across t
    const uint4* vbase = (const uint4*)(g_votes + (size_t)bco*65536) + ph*128 + t;

    float l[32];
    int S[8] = {0,0,0,0,0,0,0,0};
    const float* lgp = g_logits + (b*32)*8192 + co*256 + ph*128 + t;
    #pragma unroll
    for (int c = 0; c < 32; c++) {
        float lv = lgp[c*8192];
        l[c] = lv;
        float e = expf(lv - smaxs[c]);
        int r = __float2int_rn(__fmul_rn(__fdiv_rn(e, ssums[c]), 256.f));
        if (r) {
            uint4 vv = vbase[c*256];
            int e0, e1;
            upk(vv.x, e0, e1); S[0] += r*e0; S[1] += r*e1;
            upk(vv.y, e0, e1); S[2] += r*e0; S[3] += r*e1;
            upk(vv.z, e0, e1); S[4] += r*e0; S[5] += r*e1;
            upk(vv.w, e0, e1); S[6] += r*e0; S[7] += r*e1;
        }
    }
    float pq[8]; float ss = 0.f;
    #pragma unroll
    for (int no = 0; no < 8; no++) {
        float pre = __fadd_rn(__fmul_rn((float)S[no], 1.52587890625e-05f), sb[no]);
        float q = rintf(__fmul_rn(pre, 256.f)) * 0.00390625f;
        pq[no] = q; ss = __fadd_rn(ss, __fmul_rn(q, q));
    }
    float n   = sqrtf(ss);
    float den = __fadd_rn(1.f, __fmul_rn(n, n));
    int ai[8];
    #pragma unroll
    for (int no = 0; no < 8; no++) {
        float a = __fdiv_rn(__fmul_rn(pq[no], n), den);
        int q = __float2int_rn(__fmul_rn(a, 256.f));
        ai[no] = q;
        out[(bco*8 + no)*256 + ph*128 + t] = (float)q * 0.00390625f;
    }
    if (!last) {
        float* lw = g_logits + (b*32)*8192 + co*256 + ph*128 + t;
        #pragma unroll
        for (int c = 0; c < 32; c++) {
            uint4 vv = vbase[c*256];
            int e0, e1, m = 0;
            upk(vv.x, e0, e1); m += ai[0]*e0 + ai[1]*e1;
            upk(vv.y, e0, e1); m += ai[2]*e0 + ai[3]*e1;
            upk(vv.z, e0, e1); m += ai[4]*e0 + ai[5]*e1;
            upk(vv.w, e0, e1); m += ai[6]*e0 + ai[7]*e1;
            float lg = __fadd_rn(l[c], __fmul_rn((float)m, 1.52587890625e-05f));
            lw[c*8192] = rintf(__fmul_rn(lg, 256.f)) * 0.00390625f;
        }
    }
}

// ---------------------------------------------------------------------------
extern "C" void kernel_launch(void* const* d_in, const int* in_sizes, int n_in,
                              void* d_out, int out_size)
{
    const float* x    = (const float*)d_in[0];
    const float* w    = (const float*)d_in[1];
    const float* cb   = (const float*)d_in[2];
    const float* bias = (const float*)d_in[3];
    float* out = (float*)d_out;
    (void)in_sizes; (void)n_in; (void)out_size;

    cudaFuncSetAttribute(conv_votes_kernel, cudaFuncAttributeMaxDynamicSharedMemorySize, CONV_SMEM);

    prep_kernel<<<1024, 256>>>(x, w);                         // launch 1 (W + x split)
    conv_votes_kernel<<<1024, 512, CONV_SMEM>>>(cb, bias);    // launch 2 (+ iter 1 folded)
    softmax_kernel<<<1024, 256>>>();                          // launch 3 (iteration 2)
    route_kernel<<<2048, 128>>>(bias, out, 0);                // launch 4 -> profiled
    softmax_kernel<<<1024, 256>>>();                          // iteration 3
    route_kernel<<<2048, 128>>>(bias, out, 1);
}

// round 13
// speedup vs baseline: 1.6113x; 1.0226x over previous
#include <cuda_runtime.h>
#include <cuda_fp16.h>
#include <cstdint>

#define BSZ 32
#define CIc 32
#define PP  256

__device__ short g_votes[BSZ*32*CIc*8*PP];   // [b][co][ci][p][no], value*256 (exact)
__device__ float g_logits[BSZ*CIc*32*PP];    // [b][ci][co][p]
__device__ float g_smax[BSZ*CIc];
__device__ float g_ssum[BSZ*CIc];
__device__ float g_thr[BSZ*CIc];             // r>=1 threshold: M + ln(S/512) - margin
__device__ uint4  g_wsplit[5632];            // W fp16 hi[0..45056) lo[45056..90112), 176B rows
__device__ __half g_xh[BSZ*CIc*2048];        // x fp16 hi
__device__ __half g_xl[BSZ*CIc*2048];        // x fp16 lo

// ---------------- helpers ----------------
static __device__ __forceinline__ uint32_t smem_u32(const void* p) {
    uint32_t a;
    asm("{ .reg .u64 t; cvta.to.shared.u64 t, %1; cvt.u32.u64 %0, t; }" : "=r"(a) : "l"(p));
    return a;
}

#define MMA16816(d, a, b) \
    asm volatile("mma.sync.aligned.m16n8k16.row.col.f32.f16.f16.f32 " \
        "{%0,%1,%2,%3}, {%4,%5,%6,%7}, {%8,%9}, {%0,%1,%2,%3};" \
        : "+f"((d)[0]), "+f"((d)[1]), "+f"((d)[2]), "+f"((d)[3]) \
        : "r"((a)[0]), "r"((a)[1]), "r"((a)[2]), "r"((a)[3]), "r"((b)[0]), "r"((b)[1]))

#define MMA1688(d, a0, a1, b0) \
    asm volatile("mma.sync.aligned.m16n8k8.row.col.f32.f16.f16.f32 " \
        "{%0,%1,%2,%3}, {%4,%5}, {%6}, {%0,%1,%2,%3};" \
        : "+f"((d)[0]), "+f"((d)[1]), "+f"((d)[2]), "+f"((d)[3]) \
        : "r"(a0), "r"(a1), "r"(b0))

#define LDMX4(r0, r1, r2, r3, addr) \
    asm volatile("ldmatrix.sync.aligned.m8n8.x4.shared.b16 {%0,%1,%2,%3}, [%4];" \
        : "=r"(r0), "=r"(r1), "=r"(r2), "=r"(r3) : "r"(addr))

static __device__ __forceinline__ uint32_t packh(__half a, __half b) {
    return (uint32_t)__half_as_ushort(a) | ((uint32_t)__half_as_ushort(b) << 16);
}
static __device__ __forceinline__ uint32_t packsplit(float f0, float f1, uint32_t &lo) {
    __half h0 = __float2half_rn(f0), h1 = __float2half_rn(f1);
    __half l0 = __float2half_rn(__fsub_rn(f0, __half2float(h0)));
    __half l1 = __float2half_rn(__fsub_rn(f1, __half2float(h1)));
    lo = packh(l0, l1);
    return packh(h0, h1);
}
static __device__ __forceinline__ void upk(uint32_t u, int &a, int &b) {
    a = (int)(short)(u & 0xFFFFu);
    b = ((int)u) >> 16;
}

// 176B rows: 44*i mod 32 covers all banks -> ldmatrix conflict-free
#define ROWB       176u
#define BHI_OFF    0u
#define BLO_OFF    45056u
#define AHI_OFF    90112u
#define ALO_OFF    135168u
#define XSH_OFF    180224u
#define XSL_OFF    185408u
#define CBS_OFF    190592u
#define A1S_OFF    191616u
#define KLUT_OFF   192640u
#define CONV_SMEM  192928

// ---------------------------------------------------------------------------
// Prep: x -> fp16 hi/lo per tile; block 0 additionally splits W (layout-final)
// ---------------------------------------------------------------------------
__global__ void __launch_bounds__(256) prep_kernel(
    const float* __restrict__ x, const float* __restrict__ w)
{
    const int tile = blockIdx.x;           // b*32 + ci
    const float4* src = (const float4*)(x + tile*2048);
    #pragma unroll
    for (int i = 0; i < 2; i++) {
        int idx4 = threadIdx.x + i*256;
        float4 v = src[idx4];
        uint32_t l0, l1;
        uint32_t h0 = packsplit(v.x, v.y, l0);
        uint32_t h1 = packsplit(v.z, v.w, l1);
        *(uint2*)(g_xh + tile*2048 + idx4*4) = make_uint2(h0, h1);
        *(uint2*)(g_xl + tile*2048 + idx4*4) = make_uint2(l0, l1);
    }
    if (blockIdx.x == 0) {
        const int o = threadIdx.x;
        const float4* wr = (const float4*)(w + o*72);
        char* bh = (char*)g_wsplit + o*ROWB;
        char* bl = (char*)g_wsplit + 45056 + o*ROWB;
        #pragma unroll
        for (int q = 0; q < 18; q++) {
            float4 v = wr[q];
            uint32_t l0, l1;
            uint32_t h0 = packsplit(v.x, v.y, l0);
            uint32_t h1 = packsplit(v.z, v.w, l1);
            *(uint2*)(bh + q*8) = make_uint2(h0, h1);
            *(uint2*)(bl + q*8) = make_uint2(l0, l1);
        }
        *(uint4*)(bh + 144) = make_uint4(0,0,0,0);
        *(uint4*)(bh + 160) = make_uint4(0,0,0,0);
        *(uint4*)(bl + 144) = make_uint4(0,0,0,0);
        *(uint4*)(bl + 160) = make_uint4(0,0,0,0);
    }
}

// ---------------------------------------------------------------------------
// Kernel 1: fp16-split mma.sync conv -> int16 votes + iteration-1 logits.
// block = (b, ci), 512 threads / 16 warps. Votes [b][co][ci][p][no].
// ---------------------------------------------------------------------------
__global__ void __launch_bounds__(512, 1) conv_votes_kernel(
    const float* __restrict__ cb, const float* __restrict__ bias)
{
    extern __shared__ char sh[];
    float* cbs = (float*)(sh + CBS_OFF);
    int*   a1s = (int*)(sh + A1S_OFF);
    int*   klut= (int*)(sh + KLUT_OFF);
    const uint32_t smb = smem_u32(sh);

    const int t = threadIdx.x;
    const int wid = t >> 5, lane = t & 31;
    const int b = blockIdx.x >> 5, ci = blockIdx.x & 31;

    {
        const uint4* src = g_wsplit;
        uint4* dst = (uint4*)sh;
        #pragma unroll
        for (int i = 0; i < 11; i++) dst[t + i*512] = src[t + i*512];
    }
    {
        uint32_t* z = (uint32_t*)(sh + XSH_OFF);
        #pragma unroll
        for (int i = 0; i < 6; i++) {
            int idx = t + i*512;
            if (idx < 2592) z[idx] = 0;
        }
    }
    if (t < 256) cbs[t] = cb[t];
    if (t < 72) { int ni = t/9, r = t%9; klut[t] = ni*324 + (r/3)*18 + (r%3); }
    if (t < 32) {
        float pv[8]; float ss = 0.f;
        #pragma unroll
        for (int no = 0; no < 8; no++) {
            float q = rintf(__fmul_rn(bias[t*8+no], 256.f)) * 0.00390625f;
            pv[no] = q; ss = __fadd_rn(ss, __fmul_rn(q, q));
        }
        float n = sqrtf(ss);
        float den = __fadd_rn(1.f, __fmul_rn(n, n));
        #pragma unroll
        for (int no = 0; no < 8; no++) {
            float a = __fdiv_rn(__fmul_rn(pv[no], n), den);
            a1s[t*8+no] = __float2int_rn(__fmul_rn(a, 256.f));
        }
    }
    __syncthreads();

    {
        const __half* xh = g_xh + blockIdx.x*2048;
        const __half* xl = g_xl + blockIdx.x*2048;
        unsigned short* dh = (unsigned short*)(sh + XSH_OFF);
        unsigned short* dl = (unsigned short*)(sh + XSL_OFF);
        #pragma unroll
        for (int i = 0; i < 4; i++) {
            int idx = t + i*512;
            int ni = idx >> 8, rem = idx & 255;
            int dsto = ni*324 + ((rem>>4)+1)*18 + (rem&15) + 1;
            dh[dsto] = __half_as_ushort(xh[idx]);
            dl[dsto] = __half_as_ushort(xl[idx]);
        }
    }
    __syncthreads();
    {
        const int p = t & 255;
        const unsigned short* xsrc = (unsigned short*)(sh + ((t < 256) ? XSH_OFF : XSL_OFF));
        char* dst = sh + ((t < 256) ? AHI_OFF : ALO_OFF) + p*ROWB;
        const int xyb = (p >> 4)*18 + (p & 15);
        #pragma unroll
        for (int q = 0; q < 9; q++) {
            uint32_t u[4];
            #pragma unroll
            for (int j = 0; j < 4; j++) {
                uint32_t v0 = xsrc[klut[q*8 + 2*j]     + xyb];
                uint32_t v1 = xsrc[klut[q*8 + 2*j + 1] + xyb];
                u[j] = v0 | (v1 << 16);
            }
            *(uint4*)(dst + q*16) = make_uint4(u[0], u[1], u[2], u[3]);
        }
        *(uint4*)(dst + 144) = make_uint4(0,0,0,0);
        *(uint4*)(dst + 160) = make_uint4(0,0,0,0);
    }
    __syncthreads();

    const int pbase = (wid & 7)*32;
    const int obase = (wid >> 3)*128;
    const int lane2 = (lane & 3)*2;

    #pragma unroll 1
    for (int pass = 0; pass < 4; pass++) {
        const int otile = obase + pass*32;
        float acc[2][4][4];
        #pragma unroll
        for (int mt = 0; mt < 2; mt++)
            #pragma unroll
            for (int nt = 0; nt < 4; nt++)
                #pragma unroll
                for (int j = 0; j < 4; j++) acc[mt][nt][j] = 0.f;

        #pragma unroll
        for (int kc = 0; kc < 5; kc++) {
            uint32_t ah[2][4], al[2][4];
            #pragma unroll
            for (int mt = 0; mt < 2; mt++) {
                const uint32_t arow = pbase + mt*16 + (lane & 15);
                const uint32_t aoff = arow*ROWB + kc*32 + ((lane >> 4) << 4);
                LDMX4(ah[mt][0], ah[mt][1], ah[mt][2], ah[mt][3], smb + AHI_OFF + aoff);
                LDMX4(al[mt][0], al[mt][1], al[mt][2], al[mt][3], smb + ALO_OFF + aoff);
            }
            uint32_t bh[4][2], bl[4][2];
            #pragma unroll
            for (int g = 0; g < 2; g++) {
                const uint32_t row = otile + g*16 + (lane & 7) + ((lane >> 4) << 3);
                const uint32_t koff = kc*32 + ((lane >> 3) & 1)*16;
                LDMX4(bh[2*g][0], bh[2*g][1], bh[2*g+1][0], bh[2*g+1][1],
                      smb + BHI_OFF + row*ROWB + koff);
                LDMX4(bl[2*g][0], bl[2*g][1], bl[2*g+1][0], bl[2*g+1][1],
                      smb + BLO_OFF + row*ROWB + koff);
            }
            if (kc < 4) {
                #pragma unroll
                for (int mt = 0; mt < 2; mt++)
                    #pragma unroll
                    for (int nt = 0; nt < 4; nt++)
                        MMA16816(acc[mt][nt], ah[mt], bh[nt]);
                #pragma unroll
                for (int mt = 0; mt < 2; mt++)
                    #pragma unroll
                    for (int nt = 0; nt < 4; nt++)
                        MMA16816(acc[mt][nt], ah[mt], bl[nt]);
                #pragma unroll
                for (int mt = 0; mt < 2; mt++)
                    #pragma unroll
                    for (int nt = 0; nt < 4; nt++)
                        MMA16816(acc[mt][nt], al[mt], bh[nt]);
            } else {
                #pragma unroll
                for (int mt = 0; mt < 2; mt++)
                    #pragma unroll
                    for (int nt = 0; nt < 4; nt++)
                        MMA1688(acc[mt][nt], ah[mt][0], ah[mt][1], bh[nt][0]);
                #pragma unroll
                for (int mt = 0; mt < 2; mt++)
                    #pragma unroll
                    for (int nt = 0; nt < 4; nt++)
                        MMA1688(acc[mt][nt], ah[mt][0], ah[mt][1], bl[nt][0]);
                #pragma unroll
                for (int mt = 0; mt < 2; mt++)
                    #pragma unroll
                    for (int nt = 0; nt < 4; nt++)
                        MMA1688(acc[mt][nt], al[mt][0], al[mt][1], bh[nt][0]);
            }
        }

        // epilogue: votes [ci][p][no] (u32 pair stores) + quad-shuffle logit fold
        #pragma unroll
        for (int mt = 0; mt < 2; mt++) {
            const int p0 = pbase + mt*16 + (lane >> 2);
            #pragma unroll
            for (int nt = 0; nt < 4; nt++) {
                const int o = otile + nt*8 + lane2;     // no = lane2 (even), co = o>>3
                const float cb0 = cbs[o], cb1 = cbs[o+1];
                int v0 = __float2int_rn((acc[mt][nt][0] + cb0) * 256.f);
                int v1 = __float2int_rn((acc[mt][nt][1] + cb1) * 256.f);
                int v2 = __float2int_rn((acc[mt][nt][2] + cb0) * 256.f);
                int v3 = __float2int_rn((acc[mt][nt][3] + cb1) * 256.f);
                short* vb = g_votes + ((size_t)b << 21) + ((o >> 3)*32 + ci)*2048;
                *(uint32_t*)(vb + p0*8 + lane2)       = (v0 & 0xFFFF) | ((uint32_t)v1 << 16);
                *(uint32_t*)(vb + (p0 + 8)*8 + lane2) = (v2 & 0xFFFF) | ((uint32_t)v3 << 16);
                int s0 = a1s[o]*v0 + a1s[o+1]*v1;
                int s1 = a1s[o]*v2 + a1s[o+1]*v3;
                s0 += __shfl_xor_sync(0xffffffffu, s0, 1);
                s0 += __shfl_xor_sync(0xffffffffu, s0, 2);
                s1 += __shfl_xor_sync(0xffffffffu, s1, 1);
                s1 += __shfl_xor_sync(0xffffffffu, s1, 2);
                if ((lane & 3) == 0) {
                    float* lb = g_logits + ((b*32 + ci)*32 + (o >> 3))*256;
                    lb[p0]     = rintf((float)s0 * 0.00390625f) * 0.00390625f;
                    lb[p0 + 8] = rintf((float)s1 * 0.00390625f) * 0.00390625f;
                }
            }
        }
    }
}

// ---------------------------------------------------------------------------
// Kernel 2: softmax stats per (b, ci) over 8192 logits (+ r>=1 threshold)
// ---------------------------------------------------------------------------
__global__ void __launch_bounds__(256) softmax_kernel()
{
    const int row = blockIdx.x;
    const float* lp = g_logits + row*8192;
    const int t = threadIdx.x;
    float fl[32];
    #pragma unroll
    for (int i = 0; i < 32; i++) fl[i] = lp[i*256 + t];
    float m = fl[0];
    #pragma unroll
    for (int i = 1; i < 32; i++) m = fmaxf(m, fl[i]);
    __shared__ float red[8];
    #pragma unroll
    for (int off = 16; off; off >>= 1) m = fmaxf(m, __shfl_xor_sync(0xffffffffu, m, off));
    if ((t & 31) == 0) red[t >> 5] = m;
    __syncthreads();
    float M = red[0];
    #pragma unroll
    for (int i = 1; i < 8; i++) M = fmaxf(M, red[i]);
    __syncthreads();
    float s = 0.f;
    #pragma unroll
    for (int i = 0; i < 32; i++) s += expf(fl[i] - M);
    #pragma unroll
    for (int off = 16; off; off >>= 1) s += __shfl_xor_sync(0xffffffffu, s, off);
    if ((t & 31) == 0) red[t >> 5] = s;
    __syncthreads();
    if (t == 0) {
        float S = red[0];
        for (int i = 1; i < 8; i++) S += red[i];
        g_smax[row] = M;
        g_ssum[row] = S;
        // r >= 1 requires 256*e^(lv-M)/S > 0.5  <=>  lv >= M + ln(S/512).
        // Conservative margin (1e-3 >> log ulp) so skipped entries are
        // GUARANTEED r==0; marginal entries take the exact exp path.
        g_thr[row] = M + logf(S * 0.001953125f) - 1e-3f;
    }
}

// ---------------------------------------------------------------------------
// Kernel 3: fused routing iteration. block = (b, co, p-half); 128 threads.
// Threshold gate: exp/div/round only where r could be nonzero (bit-identical).
// ---------------------------------------------------------------------------
__global__ void __launch_bounds__(128) route_kernel(
    const float* __restrict__ bias, float* __restrict__ out, int last)
{
    __shared__ float smaxs[32], ssums[32], sthr[32], sb[8];

    const int t   = threadIdx.x;
    const int blk = blockIdx.x;
    const int bco = blk >> 1, ph = blk & 1;
    const int b   = bco >> 5, co = bco & 31;

    if (t < 32) {
        smaxs[t] = g_smax[b*32 + t];
        ssums[t] = g_ssum[b*32 + t];
        sthr[t]  = g_thr[b*32 + t];
    }
    if (t < 8)  sb[t] = bias[co*8 + t];
    __syncthreads();

    const uint4* vbase = (const uint4*)(g_votes + (size_t)bco*65536) + ph*128 + t;

    float l[32];
    int S[8] = {0,0,0,0,0,0,0,0};
    const float* lgp = g_logits + (b*32)*8192 + co*256 + ph*128 + t;
    #pragma unroll
    for (int c = 0; c < 32; c++) {
        float lv = lgp[c*8192];
        l[c] = lv;
        if (lv >= sthr[c]) {      // only here can r >= 1 (guaranteed otherwise 0)
            float e = expf(lv - smaxs[c]);
            int r = __float2int_rn(__fmul_rn(__fdiv_rn(e, ssums[c]), 256.f));
            if (r) {
                uint4 vv = vbase[c*256];
                int e0, e1;
                upk(vv.x, e0, e1); S[0] += r*e0; S[1] += r*e1;
                upk(vv.y, e0, e1); S[2] += r*e0; S[3] += r*e1;
                upk(vv.z, e0, e1); S[4] += r*e0; S[5] += r*e1;
                upk(vv.w, e0, e1); S[6] += r*e0; S[7] += r*e1;
            }
        }
    }
    float pq[8]; float ss = 0.f;
    #pragma unroll
    for (int no = 0; no < 8; no++) {
        float pre = __fadd_rn(__fmul_rn((float)S[no], 1.52587890625e-05f), sb[no]);
        float q = rintf(__fmul_rn(pre, 256.f)) * 0.00390625f;
        pq[no] = q; ss = __fadd_rn(ss, __fmul_rn(q, q));
    }
    float n   = sqrtf(ss);
    float den = __fadd_rn(1.f, __fmul_rn(n, n));
    int ai[8];
    #pragma unroll
    for (int no = 0; no < 8; no++) {
        float a = __fdiv_rn(__fmul_rn(pq[no], n), den);
        int q = __float2int_rn(__fmul_rn(a, 256.f));
        ai[no] = q;
        out[(bco*8 + no)*256 + ph*128 + t] = (float)q * 0.00390625f;
    }
    if (!last) {
        float* lw = g_logits + (b*32)*8192 + co*256 + ph*128 + t;
        #pragma unroll
        for (int c = 0; c < 32; c++) {
            uint4 vv = vbase[c*256];
            int e0, e1, m = 0;
            upk(vv.x, e0, e1); m += ai[0]*e0 + ai[1]*e1;
            upk(vv.y, e0, e1); m += ai[2]*e0 + ai[3]*e1;
            upk(vv.z, e0, e1); m += ai[4]*e0 + ai[5]*e1;
            upk(vv.w, e0, e1); m += ai[6]*e0 + ai[7]*e1;
            float lg = __fadd_rn(l[c], __fmul_rn((float)m, 1.52587890625e-05f));
            lw[c*8192] = rintf(__fmul_rn(lg, 256.f)) * 0.00390625f;
        }
    }
}

// ---------------------------------------------------------------------------
extern "C" void kernel_launch(void* const* d_in, const int* in_sizes, int n_in,
                              void* d_out, int out_size)
{
    const float* x    = (const float*)d_in[0];
    const float* w    = (const float*)d_in[1];
    const float* cb   = (const float*)d_in[2];
    const float* bias = (const float*)d_in[3];
    float* out = (float*)d_out;
    (void)in_sizes; (void)n_in; (void)out_size;

    cudaFuncSetAttribute(conv_votes_kernel, cudaFuncAttributeMaxDynamicSharedMemorySize, CONV_SMEM);

    prep_kernel<<<1024, 256>>>(x, w);                         // launch 1 (W + x split)
    conv_votes_kernel<<<1024, 512, CONV_SMEM>>>(cb, bias);    // launch 2 (+ iter 1 folded)
    softmax_kernel<<<1024, 256>>>();                          // launch 3 (iteration 2)
    route_kernel<<<2048, 128>>>(bias, out, 0);                // launch 4 -> profiled
    softmax_kernel<<<1024, 256>>>();                          // iteration 3
    route_kernel<<<2048, 128>>>(bias, out, 1);
}

// round 14
// speedup vs baseline: 1.6896x; 1.0486x over previous
#include <cuda_runtime.h>
#include <cuda_fp16.h>
#include <cstdint>

#define BSZ 32
#define CIc 32
#define PP  256

__device__ short g_votes[BSZ*32*CIc*8*PP];   // [b][co][ci][p][no], value*256 (exact)
__device__ float g_logits[BSZ*CIc*32*PP];    // [b][ci][co][p]
__device__ float g_smax[BSZ*CIc];
__device__ float g_ssum[BSZ*CIc];
__device__ float g_thr[BSZ*CIc];             // r>=1 threshold: M + ln(S/512) - margin
__device__ uint4  g_wsplit[5632];            // W fp16 hi[0..45056) lo[45056..90112), 176B rows
__device__ __half g_xh[BSZ*CIc*2048];        // x fp16 hi
__device__ __half g_xl[BSZ*CIc*2048];        // x fp16 lo

// ---------------- helpers ----------------
static __device__ __forceinline__ uint32_t smem_u32(const void* p) {
    uint32_t a;
    asm("{ .reg .u64 t; cvta.to.shared.u64 t, %1; cvt.u32.u64 %0, t; }" : "=r"(a) : "l"(p));
    return a;
}

#define MMA16816(d, a, b) \
    asm volatile("mma.sync.aligned.m16n8k16.row.col.f32.f16.f16.f32 " \
        "{%0,%1,%2,%3}, {%4,%5,%6,%7}, {%8,%9}, {%0,%1,%2,%3};" \
        : "+f"((d)[0]), "+f"((d)[1]), "+f"((d)[2]), "+f"((d)[3]) \
        : "r"((a)[0]), "r"((a)[1]), "r"((a)[2]), "r"((a)[3]), "r"((b)[0]), "r"((b)[1]))

#define MMA1688(d, a0, a1, b0) \
    asm volatile("mma.sync.aligned.m16n8k8.row.col.f32.f16.f16.f32 " \
        "{%0,%1,%2,%3}, {%4,%5}, {%6}, {%0,%1,%2,%3};" \
        : "+f"((d)[0]), "+f"((d)[1]), "+f"((d)[2]), "+f"((d)[3]) \
        : "r"(a0), "r"(a1), "r"(b0))

#define LDMX4(r0, r1, r2, r3, addr) \
    asm volatile("ldmatrix.sync.aligned.m8n8.x4.shared.b16 {%0,%1,%2,%3}, [%4];" \
        : "=r"(r0), "=r"(r1), "=r"(r2), "=r"(r3) : "r"(addr))

static __device__ __forceinline__ uint32_t packh(__half a, __half b) {
    return (uint32_t)__half_as_ushort(a) | ((uint32_t)__half_as_ushort(b) << 16);
}
static __device__ __forceinline__ uint32_t packsplit(float f0, float f1, uint32_t &lo) {
    __half h0 = __float2half_rn(f0), h1 = __float2half_rn(f1);
    __half l0 = __float2half_rn(__fsub_rn(f0, __half2float(h0)));
    __half l1 = __float2half_rn(__fsub_rn(f1, __half2float(h1)));
    lo = packh(l0, l1);
    return packh(h0, h1);
}
static __device__ __forceinline__ void upk(uint32_t u, int &a, int &b) {
    a = (int)(short)(u & 0xFFFFu);
    b = ((int)u) >> 16;
}

// 176B rows: 44*i mod 32 covers all banks -> ldmatrix conflict-free
#define ROWB       176u
#define BHI_OFF    0u
#define BLO_OFF    45056u
#define AHI_OFF    90112u
#define ALO_OFF    135168u
#define XSH_OFF    180224u
#define XSL_OFF    185408u
#define CBS_OFF    190592u
#define A1S_OFF    191616u
#define KLUT_OFF   192640u
#define CONV_SMEM  192928

// ---------------------------------------------------------------------------
// Prep: x -> fp16 hi/lo per tile; block 0 additionally splits W (layout-final)
// ---------------------------------------------------------------------------
__global__ void __launch_bounds__(256) prep_kernel(
    const float* __restrict__ x, const float* __restrict__ w)
{
    const int tile = blockIdx.x;           // b*32 + ci
    const float4* src = (const float4*)(x + tile*2048);
    #pragma unroll
    for (int i = 0; i < 2; i++) {
        int idx4 = threadIdx.x + i*256;
        float4 v = src[idx4];
        uint32_t l0, l1;
        uint32_t h0 = packsplit(v.x, v.y, l0);
        uint32_t h1 = packsplit(v.z, v.w, l1);
        *(uint2*)(g_xh + tile*2048 + idx4*4) = make_uint2(h0, h1);
        *(uint2*)(g_xl + tile*2048 + idx4*4) = make_uint2(l0, l1);
    }
    if (blockIdx.x == 0) {
        const int o = threadIdx.x;
        const float4* wr = (const float4*)(w + o*72);
        char* bh = (char*)g_wsplit + o*ROWB;
        char* bl = (char*)g_wsplit + 45056 + o*ROWB;
        #pragma unroll
        for (int q = 0; q < 18; q++) {
            float4 v = wr[q];
            uint32_t l0, l1;
            uint32_t h0 = packsplit(v.x, v.y, l0);
            uint32_t h1 = packsplit(v.z, v.w, l1);
            *(uint2*)(bh + q*8) = make_uint2(h0, h1);
            *(uint2*)(bl + q*8) = make_uint2(l0, l1);
        }
        *(uint4*)(bh + 144) = make_uint4(0,0,0,0);
        *(uint4*)(bh + 160) = make_uint4(0,0,0,0);
        *(uint4*)(bl + 144) = make_uint4(0,0,0,0);
        *(uint4*)(bl + 160) = make_uint4(0,0,0,0);
    }
}

// ---------------------------------------------------------------------------
// Kernel 1: fp16-split mma.sync conv -> int16 votes + iteration-1 logits.
// block = (b, ci), 512 threads / 16 warps. Votes [b][co][ci][p][no].
// ---------------------------------------------------------------------------
__global__ void __launch_bounds__(512, 1) conv_votes_kernel(
    const float* __restrict__ cb, const float* __restrict__ bias)
{
    extern __shared__ char sh[];
    float* cbs = (float*)(sh + CBS_OFF);
    int*   a1s = (int*)(sh + A1S_OFF);
    int*   klut= (int*)(sh + KLUT_OFF);
    const uint32_t smb = smem_u32(sh);

    const int t = threadIdx.x;
    const int wid = t >> 5, lane = t & 31;
    const int b = blockIdx.x >> 5, ci = blockIdx.x & 31;

    {
        const uint4* src = g_wsplit;
        uint4* dst = (uint4*)sh;
        #pragma unroll
        for (int i = 0; i < 11; i++) dst[t + i*512] = src[t + i*512];
    }
    {
        uint32_t* z = (uint32_t*)(sh + XSH_OFF);
        #pragma unroll
        for (int i = 0; i < 6; i++) {
            int idx = t + i*512;
            if (idx < 2592) z[idx] = 0;
        }
    }
    if (t < 256) cbs[t] = cb[t];
    if (t < 72) { int ni = t/9, r = t%9; klut[t] = ni*324 + (r/3)*18 + (r%3); }
    if (t < 32) {
        float pv[8]; float ss = 0.f;
        #pragma unroll
        for (int no = 0; no < 8; no++) {
            float q = rintf(__fmul_rn(bias[t*8+no], 256.f)) * 0.00390625f;
            pv[no] = q; ss = __fadd_rn(ss, __fmul_rn(q, q));
        }
        float n = sqrtf(ss);
        float den = __fadd_rn(1.f, __fmul_rn(n, n));
        #pragma unroll
        for (int no = 0; no < 8; no++) {
            float a = __fdiv_rn(__fmul_rn(pv[no], n), den);
            a1s[t*8+no] = __float2int_rn(__fmul_rn(a, 256.f));
        }
    }
    __syncthreads();

    {
        const __half* xh = g_xh + blockIdx.x*2048;
        const __half* xl = g_xl + blockIdx.x*2048;
        unsigned short* dh = (unsigned short*)(sh + XSH_OFF);
        unsigned short* dl = (unsigned short*)(sh + XSL_OFF);
        #pragma unroll
        for (int i = 0; i < 4; i++) {
            int idx = t + i*512;
            int ni = idx >> 8, rem = idx & 255;
            int dsto = ni*324 + ((rem>>4)+1)*18 + (rem&15) + 1;
            dh[dsto] = __half_as_ushort(xh[idx]);
            dl[dsto] = __half_as_ushort(xl[idx]);
        }
    }
    __syncthreads();
    {
        const int p = t & 255;
        const unsigned short* xsrc = (unsigned short*)(sh + ((t < 256) ? XSH_OFF : XSL_OFF));
        char* dst = sh + ((t < 256) ? AHI_OFF : ALO_OFF) + p*ROWB;
        const int xyb = (p >> 4)*18 + (p & 15);
        #pragma unroll
        for (int q = 0; q < 9; q++) {
            uint32_t u[4];
            #pragma unroll
            for (int j = 0; j < 4; j++) {
                uint32_t v0 = xsrc[klut[q*8 + 2*j]     + xyb];
                uint32_t v1 = xsrc[klut[q*8 + 2*j + 1] + xyb];
                u[j] = v0 | (v1 << 16);
            }
            *(uint4*)(dst + q*16) = make_uint4(u[0], u[1], u[2], u[3]);
        }
        *(uint4*)(dst + 144) = make_uint4(0,0,0,0);
        *(uint4*)(dst + 160) = make_uint4(0,0,0,0);
    }
    __syncthreads();

    const int pbase = (wid & 7)*32;
    const int obase = (wid >> 3)*128;
    const int lane2 = (lane & 3)*2;

    #pragma unroll 1
    for (int pass = 0; pass < 4; pass++) {
        const int otile = obase + pass*32;
        float acc[2][4][4];
        #pragma unroll
        for (int mt = 0; mt < 2; mt++)
            #pragma unroll
            for (int nt = 0; nt < 4; nt++)
                #pragma unroll
                for (int j = 0; j < 4; j++) acc[mt][nt][j] = 0.f;

        #pragma unroll
        for (int kc = 0; kc < 5; kc++) {
            uint32_t ah[2][4], al[2][4];
            #pragma unroll
            for (int mt = 0; mt < 2; mt++) {
                const uint32_t arow = pbase + mt*16 + (lane & 15);
                const uint32_t aoff = arow*ROWB + kc*32 + ((lane >> 4) << 4);
                LDMX4(ah[mt][0], ah[mt][1], ah[mt][2], ah[mt][3], smb + AHI_OFF + aoff);
                LDMX4(al[mt][0], al[mt][1], al[mt][2], al[mt][3], smb + ALO_OFF + aoff);
            }
            uint32_t bh[4][2], bl[4][2];
            #pragma unroll
            for (int g = 0; g < 2; g++) {
                const uint32_t row = otile + g*16 + (lane & 7) + ((lane >> 4) << 3);
                const uint32_t koff = kc*32 + ((lane >> 3) & 1)*16;
                LDMX4(bh[2*g][0], bh[2*g][1], bh[2*g+1][0], bh[2*g+1][1],
                      smb + BHI_OFF + row*ROWB + koff);
                LDMX4(bl[2*g][0], bl[2*g][1], bl[2*g+1][0], bl[2*g+1][1],
                      smb + BLO_OFF + row*ROWB + koff);
            }
            if (kc < 4) {
                #pragma unroll
                for (int mt = 0; mt < 2; mt++)
                    #pragma unroll
                    for (int nt = 0; nt < 4; nt++)
                        MMA16816(acc[mt][nt], ah[mt], bh[nt]);
                #pragma unroll
                for (int mt = 0; mt < 2; mt++)
                    #pragma unroll
                    for (int nt = 0; nt < 4; nt++)
                        MMA16816(acc[mt][nt], ah[mt], bl[nt]);
                #pragma unroll
                for (int mt = 0; mt < 2; mt++)
                    #pragma unroll
                    for (int nt = 0; nt < 4; nt++)
                        MMA16816(acc[mt][nt], al[mt], bh[nt]);
            } else {
                #pragma unroll
                for (int mt = 0; mt < 2; mt++)
                    #pragma unroll
                    for (int nt = 0; nt < 4; nt++)
                        MMA1688(acc[mt][nt], ah[mt][0], ah[mt][1], bh[nt][0]);
                #pragma unroll
                for (int mt = 0; mt < 2; mt++)
                    #pragma unroll
                    for (int nt = 0; nt < 4; nt++)
                        MMA1688(acc[mt][nt], ah[mt][0], ah[mt][1], bl[nt][0]);
                #pragma unroll
                for (int mt = 0; mt < 2; mt++)
                    #pragma unroll
                    for (int nt = 0; nt < 4; nt++)
                        MMA1688(acc[mt][nt], al[mt][0], al[mt][1], bh[nt][0]);
            }
        }

        // epilogue: votes [ci][p][no] (u32 pair stores) + quad-shuffle logit fold
        #pragma unroll
        for (int mt = 0; mt < 2; mt++) {
            const int p0 = pbase + mt*16 + (lane >> 2);
            #pragma unroll
            for (int nt = 0; nt < 4; nt++) {
                const int o = otile + nt*8 + lane2;     // no = lane2 (even), co = o>>3
                const float cb0 = cbs[o], cb1 = cbs[o+1];
                int v0 = __float2int_rn((acc[mt][nt][0] + cb0) * 256.f);
                int v1 = __float2int_rn((acc[mt][nt][1] + cb1) * 256.f);
                int v2 = __float2int_rn((acc[mt][nt][2] + cb0) * 256.f);
                int v3 = __float2int_rn((acc[mt][nt][3] + cb1) * 256.f);
                short* vb = g_votes + ((size_t)b << 21) + ((o >> 3)*32 + ci)*2048;
                *(uint32_t*)(vb + p0*8 + lane2)       = (v0 & 0xFFFF) | ((uint32_t)v1 << 16);
                *(uint32_t*)(vb + (p0 + 8)*8 + lane2) = (v2 & 0xFFFF) | ((uint32_t)v3 << 16);
                int s0 = a1s[o]*v0 + a1s[o+1]*v1;
                int s1 = a1s[o]*v2 + a1s[o+1]*v3;
                s0 += __shfl_xor_sync(0xffffffffu, s0, 1);
                s0 += __shfl_xor_sync(0xffffffffu, s0, 2);
                s1 += __shfl_xor_sync(0xffffffffu, s1, 1);
                s1 += __shfl_xor_sync(0xffffffffu, s1, 2);
                if ((lane & 3) == 0) {
                    float* lb = g_logits + ((b*32 + ci)*32 + (o >> 3))*256;
                    lb[p0]     = rintf((float)s0 * 0.00390625f) * 0.00390625f;
                    lb[p0 + 8] = rintf((float)s1 * 0.00390625f) * 0.00390625f;
                }
            }
        }
    }
}

// ---------------------------------------------------------------------------
// Kernel 2: softmax stats per (b, ci) over 8192 logits (+ r>=1 threshold)
// ---------------------------------------------------------------------------
__global__ void __launch_bounds__(256) softmax_kernel()
{
    const int row = blockIdx.x;
    const float* lp = g_logits + row*8192;
    const int t = threadIdx.x;
    float fl[32];
    #pragma unroll
    for (int i = 0; i < 32; i++) fl[i] = lp[i*256 + t];
    float m = fl[0];
    #pragma unroll
    for (int i = 1; i < 32; i++) m = fmaxf(m, fl[i]);
    __shared__ float red[8];
    #pragma unroll
    for (int off = 16; off; off >>= 1) m = fmaxf(m, __shfl_xor_sync(0xffffffffu, m, off));
    if ((t & 31) == 0) red[t >> 5] = m;
    __syncthreads();
    float M = red[0];
    #pragma unroll
    for (int i = 1; i < 8; i++) M = fmaxf(M, red[i]);
    __syncthreads();
    float s = 0.f;
    #pragma unroll
    for (int i = 0; i < 32; i++) s += expf(fl[i] - M);
    #pragma unroll
    for (int off = 16; off; off >>= 1) s += __shfl_xor_sync(0xffffffffu, s, off);
    if ((t & 31) == 0) red[t >> 5] = s;
    __syncthreads();
    if (t == 0) {
        float S = red[0];
        for (int i = 1; i < 8; i++) S += red[i];
        g_smax[row] = M;
        g_ssum[row] = S;
        // r >= 1 requires 256*e^(lv-M)/S > 0.5  <=>  lv >= M + ln(S/512).
        g_thr[row] = M + logf(S * 0.001953125f) - 1e-3f;
    }
}

// ---------------------------------------------------------------------------
// Kernel 3: fused routing iteration. block = (bco, ph); 256 threads =
// (p 0..127) x (c-half 0..1). Each half walks 16 c's; exact-int partial S
// reduced via smem (order-invariant) -> bit-identical results, half the
// serial latency chain per warp and 2x the warps.
// ---------------------------------------------------------------------------
__global__ void __launch_bounds__(256) route_kernel(
    const float* __restrict__ bias, float* __restrict__ out, int last)
{
    __shared__ float smaxs[32], ssums[32], sthr[32], sb[8];
    __shared__ int sS[2][128][8];    // partial S per (chalf, p, no)
    __shared__ int sai[128][8];      // activation ints per (p, no)

    const int t   = threadIdx.x;
    const int th  = t & 127;         // p index within half
    const int chh = t >> 7;          // c-half (0: c 0..15, 1: c 16..31)
    const int blk = blockIdx.x;
    const int bco = blk >> 1, ph = blk & 1;
    const int b   = bco >> 5, co = bco & 31;

    if (t < 32) {
        smaxs[t] = g_smax[b*32 + t];
        ssums[t] = g_ssum[b*32 + t];
        sthr[t]  = g_thr[b*32 + t];
    }
    if (t < 8)  sb[t] = bias[co*8 + t];
    __syncthreads();

    const uint4* vbase = (const uint4*)(g_votes + (size_t)bco*65536) + ph*128 + th;
    const float* lgp = g_logits + (size_t)(b*32 + chh*16)*8192 + co*256 + ph*128 + th;

    float l[16];
    int S[8] = {0,0,0,0,0,0,0,0};
    #pragma unroll
    for (int i = 0; i < 16; i++) {
        const int c = chh*16 + i;
        float lv = lgp[i*8192];
        l[i] = lv;
        if (lv >= sthr[c]) {      // only here can r >= 1 (guaranteed otherwise 0)
            float e = expf(lv - smaxs[c]);
            int r = __float2int_rn(__fmul_rn(__fdiv_rn(e, ssums[c]), 256.f));
            if (r) {
                uint4 vv = vbase[c*256];
                int e0, e1;
                upk(vv.x, e0, e1); S[0] += r*e0; S[1] += r*e1;
                upk(vv.y, e0, e1); S[2] += r*e0; S[3] += r*e1;
                upk(vv.z, e0, e1); S[4] += r*e0; S[5] += r*e1;
                upk(vv.w, e0, e1); S[6] += r*e0; S[7] += r*e1;
            }
        }
    }
    #pragma unroll
    for (int no = 0; no < 8; no++) sS[chh][th][no] = S[no];
    __syncthreads();

    if (chh == 0) {
        float pq[8]; float ss = 0.f;
        #pragma unroll
        for (int no = 0; no < 8; no++) {
            int St = sS[0][th][no] + sS[1][th][no];      // exact int
            float pre = __fadd_rn(__fmul_rn((float)St, 1.52587890625e-05f), sb[no]);
            float q = rintf(__fmul_rn(pre, 256.f)) * 0.00390625f;
            pq[no] = q; ss = __fadd_rn(ss, __fmul_rn(q, q));
        }
        float n   = sqrtf(ss);
        float den = __fadd_rn(1.f, __fmul_rn(n, n));
        #pragma unroll
        for (int no = 0; no < 8; no++) {
            float a = __fdiv_rn(__fmul_rn(pq[no], n), den);
            int q = __float2int_rn(__fmul_rn(a, 256.f));
            sai[th][no] = q;
            out[(bco*8 + no)*256 + ph*128 + th] = (float)q * 0.00390625f;
        }
    }
    __syncthreads();

    if (!last) {
        int ai[8];
        #pragma unroll
        for (int no = 0; no < 8; no++) ai[no] = sai[th][no];
        float* lw = g_logits + (size_t)(b*32 + chh*16)*8192 + co*256 + ph*128 + th;
        #pragma unroll
        for (int i = 0; i < 16; i++) {
            const int c = chh*16 + i;
            uint4 vv = vbase[c*256];
            int e0, e1, m = 0;
            upk(vv.x, e0, e1); m += ai[0]*e0 + ai[1]*e1;
            upk(vv.y, e0, e1); m += ai[2]*e0 + ai[3]*e1;
            upk(vv.z, e0, e1); m += ai[4]*e0 + ai[5]*e1;
            upk(vv.w, e0, e1); m += ai[6]*e0 + ai[7]*e1;
            float lg = __fadd_rn(l[i], __fmul_rn((float)m, 1.52587890625e-05f));
            lw[i*8192] = rintf(__fmul_rn(lg, 256.f)) * 0.00390625f;
        }
    }
}

// ---------------------------------------------------------------------------
extern "C" void kernel_launch(void* const* d_in, const int* in_sizes, int n_in,
                              void* d_out, int out_size)
{
    const float* x    = (const float*)d_in[0];
    const float* w    = (const float*)d_in[1];
    const float* cb   = (const float*)d_in[2];
    const float* bias = (const float*)d_in[3];
    float* out = (float*)d_out;
    (void)in_sizes; (void)n_in; (void)out_size;

    cudaFuncSetAttribute(conv_votes_kernel, cudaFuncAttributeMaxDynamicSharedMemorySize, CONV_SMEM);

    prep_kernel<<<1024, 256>>>(x, w);                         // launch 1 (W + x split)
    conv_votes_kernel<<<1024, 512, CONV_SMEM>>>(cb, bias);    // launch 2 (+ iter 1 folded)
    softmax_kernel<<<1024, 256>>>();                          // launch 3 (iteration 2)
    route_kernel<<<2048, 256>>>(bias, out, 0);                // launch 4 -> profiled
    softmax_kernel<<<1024, 256>>>();                          // iteration 3
    route_kernel<<<2048, 256>>>(bias, out, 1);
}